// round 13
// baseline (speedup 1.0000x reference)
#include <cuda_runtime.h>
#include <cuda_fp16.h>
#include <stdint.h>

#define BATCH 2
#define SEQ   2048
#define DMODEL 2048
#define NHEAD 16
#define HDIM  128
#define HID   5888
#define TOK   (BATCH*SEQ)            // 4096
#define CH    ((size_t)TOK*DMODEL)   // 8388608
#define KC2   7936                   // DMODEL + HID (fused O+FFN2 K dim)
#define EPSV  1e-5f
#define SCALE_ATT 0.08838834764831845f

#define WQKVO_SZ ((size_t)DMODEL*DMODEL)
#define W12_SZ   ((size_t)HID*DMODEL)
#define HTOT (7*CH + (size_t)TOK*KC2 + 3*WQKVO_SZ + W12_SZ + (size_t)DMODEL*KC2)

__device__ __half g_h[HTOT];
__device__ float g_bias[DMODEL];     // wo_b + w2_b

// ---------------- helpers ---------------------------------------------------
__device__ __forceinline__ uint32_t smem_u32(const void* p) {
    uint32_t a;
    asm("{ .reg .u64 t; cvta.to.shared.u64 t, %1; cvt.u32.u64 %0, t; }"
        : "=r"(a) : "l"(p));
    return a;
}
__device__ __forceinline__ uint32_t packh2(float a, float b) {
    __half2 h = __floats2half2_rn(a, b);
    return *(uint32_t*)&h;
}
__device__ __forceinline__ void cpasync16(uint32_t dst, const void* src) {
    asm volatile("cp.async.cg.shared.global [%0], [%1], 16;" :: "r"(dst), "l"(src) : "memory");
}
#define CP_COMMIT() asm volatile("cp.async.commit_group;" ::: "memory")
#define CP_WAIT2()  asm volatile("cp.async.wait_group 2;" ::: "memory")

#define LDSM4(r, addr) \
    asm volatile("ldmatrix.sync.aligned.m8n8.x4.shared.b16 {%0,%1,%2,%3}, [%4];" \
        : "=r"((r)[0]), "=r"((r)[1]), "=r"((r)[2]), "=r"((r)[3]) : "r"(addr))
#define LDSM4T(r, addr) \
    asm volatile("ldmatrix.sync.aligned.m8n8.x4.trans.shared.b16 {%0,%1,%2,%3}, [%4];" \
        : "=r"((r)[0]), "=r"((r)[1]), "=r"((r)[2]), "=r"((r)[3]) : "r"(addr))

__device__ __forceinline__ void mma_h(float (&c)[4], const uint32_t (&a)[4],
                                      uint32_t b0, uint32_t b1) {
    asm volatile(
        "mma.sync.aligned.m16n8k16.row.col.f32.f16.f16.f32 "
        "{%0,%1,%2,%3}, {%4,%5,%6,%7}, {%8,%9}, {%0,%1,%2,%3};\n"
        : "+f"(c[0]), "+f"(c[1]), "+f"(c[2]), "+f"(c[3])
        : "r"(a[0]), "r"(a[1]), "r"(a[2]), "r"(a[3]), "r"(b0), "r"(b1));
}

// ---------------- fused fp32 -> fp16 weight conversion ----------------------
// z: 0=wq 1=wk 2=wv 3=wo(->wow2 cols 0-2047) 4=w1 5=w2(->wow2 cols 2048+)
__global__ __launch_bounds__(256) void round_h6_kernel(
    const float4* __restrict__ s0, const float4* __restrict__ s1,
    const float4* __restrict__ s2, const float4* __restrict__ s3,
    const float4* __restrict__ s4, const float4* __restrict__ s5,
    uint2* __restrict__ d0, uint2* __restrict__ d1,
    uint2* __restrict__ d2, __half* __restrict__ dcw,
    uint2* __restrict__ d4,
    int nw4, int nh4)
{
    const int z = blockIdx.y;
    const int n4 = (z == 3 || z < 3) ? nw4 : nh4;
    const int i = blockIdx.x * 256 + threadIdx.x;
    if (i >= n4) return;
    const float4* in = (z == 0) ? s0 : (z == 1) ? s1 : (z == 2) ? s2
                     : (z == 3) ? s3 : (z == 4) ? s4 : s5;
    float4 v = in[i];
    uint2 u;
    u.x = packh2(v.x, v.y);
    u.y = packh2(v.z, v.w);
    if (z < 3) {
        uint2* out = (z == 0) ? d0 : (z == 1) ? d1 : d2;
        out[i] = u;
    } else if (z == 4) {
        d4[i] = u;
    } else if (z == 3) {
        const int e = i * 4;
        const int n = e >> 11, kk = e & 2047;
        *(uint2*)(dcw + (size_t)n * KC2 + kk) = u;
    } else {
        const int e = i * 4;
        const int n = e / HID, kk = e - n * HID;
        *(uint2*)(dcw + (size_t)n * KC2 + DMODEL + kk) = u;
    }
}

__global__ __launch_bounds__(256) void bias_sum_kernel(
    const float* __restrict__ a, const float* __restrict__ b,
    float* __restrict__ c)
{
    const int i = blockIdx.x * 256 + threadIdx.x;
    if (i < DMODEL) c[i] = a[i] + b[i];
}

// ---------------- fused layernorm x4 (fp32 in, fp16 out) --------------------
__global__ __launch_bounds__(256) void layernorm4_kernel(
    const float* __restrict__ x0, const float* __restrict__ x1,
    const float* __restrict__ x2, const float* __restrict__ x3,
    const float* __restrict__ w0, const float* __restrict__ w1,
    const float* __restrict__ w2, const float* __restrict__ w3,
    const float* __restrict__ b0p, const float* __restrict__ b1p,
    const float* __restrict__ b2p, const float* __restrict__ b3p,
    __half* __restrict__ o0p, __half* __restrict__ o1p,
    __half* __restrict__ o2p, __half* __restrict__ o3p)
{
    const int z = blockIdx.y;
    const float* x = (z == 0) ? x0 : (z == 1) ? x1 : (z == 2) ? x2 : x3;
    const float* w = (z == 0) ? w0 : (z == 1) ? w1 : (z == 2) ? w2 : w3;
    const float* b = (z == 0) ? b0p : (z == 1) ? b1p : (z == 2) ? b2p : b3p;
    __half* out    = (z == 0) ? o0p : (z == 1) ? o1p : (z == 2) ? o2p : o3p;

    const int row = blockIdx.x;
    const int t = threadIdx.x;
    const float4* xp = (const float4*)(x + (size_t)row * DMODEL);
    float4 v0 = xp[t], v1 = xp[t + 256];
    float s  = v0.x + v0.y + v0.z + v0.w + v1.x + v1.y + v1.z + v1.w;
    float ss = v0.x*v0.x + v0.y*v0.y + v0.z*v0.z + v0.w*v0.w
             + v1.x*v1.x + v1.y*v1.y + v1.z*v1.z + v1.w*v1.w;
    __shared__ float sred[16];
    const int lane = t & 31, warp = t >> 5;
#pragma unroll
    for (int o = 16; o; o >>= 1) {
        s  += __shfl_xor_sync(0xffffffffu, s,  o);
        ss += __shfl_xor_sync(0xffffffffu, ss, o);
    }
    if (lane == 0) { sred[warp] = s; sred[8 + warp] = ss; }
    __syncthreads();
    if (t < 32) {
        s  = (t < 8) ? sred[t]     : 0.f;
        ss = (t < 8) ? sred[8 + t] : 0.f;
#pragma unroll
        for (int o = 4; o; o >>= 1) {
            s  += __shfl_xor_sync(0xffffffffu, s,  o);
            ss += __shfl_xor_sync(0xffffffffu, ss, o);
        }
        if (t == 0) { sred[0] = s; sred[1] = ss; }
    }
    __syncthreads();
    const float mean = sred[0] * (1.f / DMODEL);
    const float var  = sred[1] * (1.f / DMODEL) - mean * mean;
    const float inv  = rsqrtf(var + EPSV);
    const float4* wp = (const float4*)w;
    const float4* bp = (const float4*)b;
    float4 wv0 = wp[t], wv1 = wp[t + 256], bv0 = bp[t], bv1 = bp[t + 256];
    uint2 u0, u1;
    u0.x = packh2((v0.x - mean) * inv * wv0.x + bv0.x, (v0.y - mean) * inv * wv0.y + bv0.y);
    u0.y = packh2((v0.z - mean) * inv * wv0.z + bv0.z, (v0.w - mean) * inv * wv0.w + bv0.w);
    u1.x = packh2((v1.x - mean) * inv * wv1.x + bv1.x, (v1.y - mean) * inv * wv1.y + bv1.y);
    u1.y = packh2((v1.z - mean) * inv * wv1.z + bv1.z, (v1.w - mean) * inv * wv1.w + bv1.w);
    uint2* op = (uint2*)(out + (size_t)row * DMODEL);
    op[t] = u0;
    op[t + 256] = u1;
}

// ------- pipelined fp16 mma GEMM: C[., c_off + 0..N) = A[M,K] @ Bw[N,K]^T ---
#define ACT_NONE 0
#define ACT_GELU 1
#define GSTAGE 49152
#define GSMEM  (4 * GSTAGE)     // 192 KB

template <int ACT, bool RES, bool OUTH>
__global__ __launch_bounds__(256, 1) void gemm_h_kernel(
    const __half* __restrict__ A, const __half* __restrict__ Bw,
    const float* __restrict__ bias0, const float* __restrict__ bias1,
    const float* __restrict__ bias2, const float* __restrict__ Resid,
    void* __restrict__ Cv, int M, int N, int K, int ldC, int c_off,
    size_t aZ, size_t wZ, size_t cZ)
{
    extern __shared__ char smem[];
    const uint32_t s0 = smem_u32(smem);
    const int tid = threadIdx.x;
    const int warp = tid >> 5, lane = tid & 31;
    const int wm = (warp & 1) << 6;
    const int wn = (warp >> 1) << 6;
    const int l15 = lane & 15, lh = lane >> 4;
    const int z = blockIdx.z;
    const float* bias = (z == 0) ? bias0 : (z == 1) ? bias1 : bias2;
    const __half* Ab = A  + (size_t)z * aZ + (size_t)(blockIdx.y * 128) * K;
    const __half* Bb = Bw + (size_t)z * wZ + (size_t)(blockIdx.x * 256) * K;
    const int nk = K >> 6;

#define G_LOAD(kt)                                                            \
    {                                                                         \
        const int st_ = (kt) & 3;                                             \
        const uint32_t sA_ = s0 + st_ * GSTAGE;                               \
        const uint32_t sB_ = sA_ + 16384;                                     \
        const size_t kof_ = (size_t)(kt) * 64;                                \
        _Pragma("unroll")                                                     \
        for (int p = 0; p < 4; ++p) {                                         \
            const int cid = tid + (p << 8);                                   \
            const int row = cid >> 3, c4 = cid & 7;                           \
            const uint32_t sw = row * 128 + ((c4 ^ (row & 7)) << 4);          \
            cpasync16(sA_ + sw, Ab + (size_t)row * K + kof_ + c4 * 8);        \
        }                                                                     \
        _Pragma("unroll")                                                     \
        for (int p = 0; p < 8; ++p) {                                         \
            const int cid = tid + (p << 8);                                   \
            const int row = cid >> 3, c4 = cid & 7;                           \
            const uint32_t sw = row * 128 + ((c4 ^ (row & 7)) << 4);          \
            cpasync16(sB_ + sw, Bb + (size_t)row * K + kof_ + c4 * 8);        \
        }                                                                     \
    }

    G_LOAD(0); CP_COMMIT();
    G_LOAD(1); CP_COMMIT();
    G_LOAD(2); CP_COMMIT();

    float acc[4][8][4];
#pragma unroll
    for (int i = 0; i < 4; i++)
#pragma unroll
        for (int j = 0; j < 8; j++)
#pragma unroll
            for (int r = 0; r < 4; r++) acc[i][j][r] = 0.f;

    for (int kt = 0; kt < nk; ++kt) {
        CP_WAIT2();
        __syncthreads();
        if (kt + 3 < nk) G_LOAD(kt + 3);
        CP_COMMIT();

        const uint32_t sA = s0 + (kt & 3) * GSTAGE, sB = sA + 16384;
#pragma unroll
        for (int kk = 0; kk < 4; ++kk) {
            uint32_t af[4][4], bf[4][4];
            const int ch = (kk << 1) + lh;
#pragma unroll
            for (int i = 0; i < 4; ++i) {
                const int row = wm + i * 16 + l15;
                LDSM4(af[i], sA + row * 128 + ((ch ^ (row & 7)) << 4));
            }
#pragma unroll
            for (int jp = 0; jp < 4; ++jp) {
                const int row = wn + jp * 16 + l15;
                LDSM4(bf[jp], sB + row * 128 + ((ch ^ (row & 7)) << 4));
            }
#pragma unroll
            for (int i = 0; i < 4; ++i)
#pragma unroll
                for (int jp = 0; jp < 4; ++jp) {
                    mma_h(acc[i][2*jp],   af[i], bf[jp][0], bf[jp][2]);
                    mma_h(acc[i][2*jp+1], af[i], bf[jp][1], bf[jp][3]);
                }
        }
    }
#undef G_LOAD

    const int g = lane >> 2, tg = lane & 3;
    const int rowbase = blockIdx.y * 128 + wm;
    const int colbase = blockIdx.x * 256 + wn;
#pragma unroll
    for (int i = 0; i < 4; ++i) {
#pragma unroll
        for (int j = 0; j < 8; ++j) {
            const int r0 = rowbase + i * 16 + g;
            const int c0 = colbase + j * 8 + tg * 2;
            const float bia0 = bias[c0], bia1 = bias[c0 + 1];
#pragma unroll
            for (int hr = 0; hr < 2; ++hr) {
                const int row = r0 + hr * 8;
                float v0 = acc[i][j][hr * 2 + 0] + bia0;
                float v1 = acc[i][j][hr * 2 + 1] + bia1;
                if (RES) {
                    v0 += Resid[(size_t)row * N + c0];
                    v1 += Resid[(size_t)row * N + c0 + 1];
                }
                if (ACT == ACT_GELU) {
                    v0 = 0.5f * v0 * (1.f + erff(v0 * 0.7071067811865475f));
                    v1 = 0.5f * v1 * (1.f + erff(v1 * 0.7071067811865475f));
                }
                if (OUTH) {
                    __half* Cb = (__half*)Cv + (size_t)z * cZ;
                    *(uint32_t*)&Cb[(size_t)row * ldC + c_off + c0] = packh2(v0, v1);
                } else {
                    float* Cb = (float*)Cv + (size_t)z * cZ;
                    *(float2*)&Cb[(size_t)row * ldC + c_off + c0] = make_float2(v0, v1);
                }
            }
        }
    }
}

// ---------------- per-head rmsnorm + rope (fp16 in-place, single tensor) ----
__global__ __launch_bounds__(256) void qknorm_rope_kernel(
    __half* __restrict__ x, const float* __restrict__ w,
    const float* __restrict__ freqs)
{
    const int token = blockIdx.x;
    const int pos = token & (SEQ - 1);
    const int warp = threadIdx.x >> 5, lane = threadIdx.x & 31;
    __shared__ float rb[8][32];
    const float4 wv = ((const float4*)w)[lane];
#pragma unroll
    for (int hh = 0; hh < 2; hh++) {
        const int h = warp + hh * 8;
        __half* p = x + (size_t)token * DMODEL + h * HDIM;
        uint2 raw = ((uint2*)p)[lane];
        const __half2 h0 = *(__half2*)&raw.x, h1 = *(__half2*)&raw.y;
        float v0 = __low2float(h0), v1 = __high2float(h0);
        float v2 = __low2float(h1), v3 = __high2float(h1);
        float ssq = v0*v0 + v1*v1 + v2*v2 + v3*v3;
#pragma unroll
        for (int o = 16; o; o >>= 1) ssq += __shfl_xor_sync(0xffffffffu, ssq, o);
        const float inv = rsqrtf(ssq * (1.f / HDIM) + EPSV);
        float o0 = v0 * inv * wv.x, o1 = v1 * inv * wv.y;
        float o2 = v2 * inv * wv.z, o3 = v3 * inv * wv.w;
        const int d0 = lane * 4;
        if (d0 < 32) {
            rb[warp][d0] = o0; rb[warp][d0 + 1] = o1;
            rb[warp][d0 + 2] = o2; rb[warp][d0 + 3] = o3;
        }
        __syncwarp();
        if (d0 < 32) {
            float r[4];
#pragma unroll
            for (int i = 0; i < 4; i++) {
                const int d = d0 + i, ii = d >> 1;
                const float x1 = rb[warp][ii], x2 = rb[warp][ii + 16];
                const float c  = freqs[pos * 32 + ii * 2];
                const float sn = freqs[pos * 32 + ii * 2 + 1];
                r[i] = (d & 1) ? (x2 * c + x1 * sn) : (x1 * c - x2 * sn);
            }
            o0 = r[0]; o1 = r[1]; o2 = r[2]; o3 = r[3];
        }
        __syncwarp();
        raw.x = packh2(o0, o1);
        raw.y = packh2(o2, o3);
        ((uint2*)p)[lane] = raw;
    }
}

// ---------------- causal flash attention (fp16 mma), per-batch --------------
#define ASTAGE 16384
#define ASMEM  (4 * ASTAGE)

__global__ __launch_bounds__(128, 3) void attn_h_kernel(
    const __half* __restrict__ Q, const __half* __restrict__ Kx,
    const __half* __restrict__ Vx, __half* __restrict__ O, int b)
{
    extern __shared__ char smem[];
    const uint32_t s0 = smem_u32(smem);
    const int tid = threadIdx.x;
    const int warp = tid >> 5, lane = tid & 31;
    const int g = lane >> 2, tg = lane & 3;
    const int l15 = lane & 15, lh = lane >> 4;
    const int qb = gridDim.x - 1 - blockIdx.x;
    const int h = blockIdx.y;
    const size_t base = ((size_t)b * SEQ) * DMODEL + h * HDIM;
    const size_t obase = ((size_t)b * SEQ) * KC2 + h * HDIM;
    const int q0 = qb * 64;
    const int wq = warp * 16;
    const int nkt = (q0 >> 5) + 2;
    const int r0 = q0 + wq + g, r1 = r0 + 8;

    uint32_t aq[8][4];
    {
        const __half* q_r0 = Q + base + (size_t)r0 * DMODEL;
        const __half* q_r1 = q_r0 + (size_t)8 * DMODEL;
#pragma unroll
        for (int kk = 0; kk < 8; ++kk) {
            aq[kk][0] = *(const uint32_t*)(q_r0 + kk * 16 + tg * 2);
            aq[kk][1] = *(const uint32_t*)(q_r1 + kk * 16 + tg * 2);
            aq[kk][2] = *(const uint32_t*)(q_r0 + kk * 16 + 8 + tg * 2);
            aq[kk][3] = *(const uint32_t*)(q_r1 + kk * 16 + 8 + tg * 2);
        }
    }

#define A_LOAD(kt)                                                            \
    {                                                                         \
        const int st_ = (kt) & 3;                                             \
        const uint32_t Kst_ = s0 + st_ * ASTAGE;                              \
        const uint32_t Vst_ = Kst_ + 8192;                                    \
        const int kv0_ = (kt) << 5;                                           \
        _Pragma("unroll")                                                     \
        for (int p = 0; p < 4; ++p) {                                         \
            const int cid = tid + (p << 7);                                   \
            const int row = cid >> 4, c = cid & 15;                           \
            const uint32_t sw = row * 256 + ((c ^ (row & 7)) << 4);           \
            const size_t go = base + (size_t)(kv0_ + row) * DMODEL + c * 8;   \
            cpasync16(Kst_ + sw, Kx + go);                                    \
            cpasync16(Vst_ + sw, Vx + go);                                    \
        }                                                                     \
    }

    A_LOAD(0); CP_COMMIT();
    A_LOAD(1); CP_COMMIT();
    A_LOAD(2); CP_COMMIT();

    float m0 = -1e30f, m1 = -1e30f, l0 = 0.f, l1 = 0.f;
    float o[16][4];
#pragma unroll
    for (int nb = 0; nb < 16; ++nb)
#pragma unroll
        for (int r = 0; r < 4; ++r) o[nb][r] = 0.f;

    for (int kt = 0; kt < nkt; ++kt) {
        CP_WAIT2();
        __syncthreads();
        if (kt + 3 < nkt) A_LOAD(kt + 3);
        CP_COMMIT();

        const int kv0 = kt << 5;
        if (kv0 <= q0 + wq + 15) {
            const uint32_t Kst = s0 + (kt & 3) * ASTAGE;
            const uint32_t Vst = Kst + 8192;

            float sc[4][4];
#pragma unroll
            for (int jb = 0; jb < 4; ++jb)
#pragma unroll
                for (int r = 0; r < 4; ++r) sc[jb][r] = 0.f;
#pragma unroll
            for (int kk = 0; kk < 8; ++kk) {
                const int ch = (kk << 1) + lh;
#pragma unroll
                for (int jp = 0; jp < 2; ++jp) {
                    uint32_t bf[4];
                    const int row = jp * 16 + l15;
                    LDSM4(bf, Kst + row * 256 + ((ch ^ (row & 7)) << 4));
                    mma_h(sc[2*jp],   aq[kk], bf[0], bf[2]);
                    mma_h(sc[2*jp+1], aq[kk], bf[1], bf[3]);
                }
            }

            const bool diag = (kv0 + 31 > r0) || (kv0 + 31 > r1);
#pragma unroll
            for (int jb = 0; jb < 4; ++jb) {
                const int c0 = kv0 + jb * 8 + tg * 2;
                sc[jb][0] *= SCALE_ATT; sc[jb][1] *= SCALE_ATT;
                sc[jb][2] *= SCALE_ATT; sc[jb][3] *= SCALE_ATT;
                if (diag) {
                    if (c0     > r0) sc[jb][0] = -1e30f;
                    if (c0 + 1 > r0) sc[jb][1] = -1e30f;
                    if (c0     > r1) sc[jb][2] = -1e30f;
                    if (c0 + 1 > r1) sc[jb][3] = -1e30f;
                }
            }

            float rm0 = sc[0][0], rm1 = sc[0][2];
#pragma unroll
            for (int jb = 0; jb < 4; ++jb) {
                rm0 = fmaxf(rm0, fmaxf(sc[jb][0], sc[jb][1]));
                rm1 = fmaxf(rm1, fmaxf(sc[jb][2], sc[jb][3]));
            }
            rm0 = fmaxf(rm0, __shfl_xor_sync(0xffffffffu, rm0, 1));
            rm0 = fmaxf(rm0, __shfl_xor_sync(0xffffffffu, rm0, 2));
            rm1 = fmaxf(rm1, __shfl_xor_sync(0xffffffffu, rm1, 1));
            rm1 = fmaxf(rm1, __shfl_xor_sync(0xffffffffu, rm1, 2));
            const float mx0 = fmaxf(m0, rm0), mx1 = fmaxf(m1, rm1);
            const float corr0 = __expf(m0 - mx0), corr1 = __expf(m1 - mx1);
            float rs0 = 0.f, rs1 = 0.f;
#pragma unroll
            for (int jb = 0; jb < 4; ++jb) {
                sc[jb][0] = __expf(sc[jb][0] - mx0);
                sc[jb][1] = __expf(sc[jb][1] - mx0);
                sc[jb][2] = __expf(sc[jb][2] - mx1);
                sc[jb][3] = __expf(sc[jb][3] - mx1);
                rs0 += sc[jb][0] + sc[jb][1];
                rs1 += sc[jb][2] + sc[jb][3];
            }
            rs0 += __shfl_xor_sync(0xffffffffu, rs0, 1);
            rs0 += __shfl_xor_sync(0xffffffffu, rs0, 2);
            rs1 += __shfl_xor_sync(0xffffffffu, rs1, 1);
            rs1 += __shfl_xor_sync(0xffffffffu, rs1, 2);
            l0 = l0 * corr0 + rs0;  m0 = mx0;
            l1 = l1 * corr1 + rs1;  m1 = mx1;
#pragma unroll
            for (int nb = 0; nb < 16; ++nb) {
                o[nb][0] *= corr0; o[nb][1] *= corr0;
                o[nb][2] *= corr1; o[nb][3] *= corr1;
            }

#pragma unroll
            for (int kc = 0; kc < 2; ++kc) {
                uint32_t pa[4];
                pa[0] = packh2(sc[2*kc][0],   sc[2*kc][1]);
                pa[1] = packh2(sc[2*kc][2],   sc[2*kc][3]);
                pa[2] = packh2(sc[2*kc+1][0], sc[2*kc+1][1]);
                pa[3] = packh2(sc[2*kc+1][2], sc[2*kc+1][3]);
#pragma unroll
                for (int cp = 0; cp < 8; ++cp) {
                    uint32_t vf[4];
                    const int row = kc * 16 + l15;
                    const int ch = (cp << 1) + lh;
                    LDSM4T(vf, Vst + row * 256 + ((ch ^ (row & 7)) << 4));
                    mma_h(o[2*cp],   pa, vf[0], vf[1]);
                    mma_h(o[2*cp+1], pa, vf[2], vf[3]);
                }
            }
        }
    }
#undef A_LOAD

    const float inv0 = 1.f / l0, inv1 = 1.f / l1;
    __half* o_r0 = O + obase + (size_t)r0 * KC2;
    __half* o_r1 = O + obase + (size_t)r1 * KC2;
#pragma unroll
    for (int nb = 0; nb < 16; ++nb) {
        const int c = nb * 8 + tg * 2;
        *(uint32_t*)&o_r0[c] = packh2(o[nb][0] * inv0, o[nb][1] * inv0);
        *(uint32_t*)&o_r1[c] = packh2(o[nb][2] * inv1, o[nb][3] * inv1);
    }
}

// ---------------- launcher --------------------------------------------------
static cudaStream_t g_side = nullptr, g_side2 = nullptr, g_side3 = nullptr;
static cudaEvent_t g_ev0 = nullptr, g_evc = nullptr, g_evln = nullptr,
                   g_evj = nullptr, g_evk = nullptr, g_evrk = nullptr,
                   g_evq = nullptr, g_evrq = nullptr, g_evv = nullptr,
                   g_evA1 = nullptr, g_evF1 = nullptr;

extern "C" void kernel_launch(void* const* d_in, const int* in_sizes, int n_in,
                              void* d_out, int out_size)
{
    const float* x0      = (const float*)d_in[0];
    const float* x1      = (const float*)d_in[1];
    const float* x2      = (const float*)d_in[2];
    const float* x3      = (const float*)d_in[3];
    const float* freqs   = (const float*)d_in[5];
    const float* wq_w    = (const float*)d_in[7];
    const float* wq_b    = (const float*)d_in[8];
    const float* wk_w    = (const float*)d_in[9];
    const float* wk_b    = (const float*)d_in[10];
    const float* wv_w    = (const float*)d_in[11];
    const float* wv_b    = (const float*)d_in[12];
    const float* wo_w    = (const float*)d_in[13];
    const float* wo_b    = (const float*)d_in[14];
    const float* qn_w    = (const float*)d_in[15];
    const float* kn_w    = (const float*)d_in[16];
    const float* ln0_w   = (const float*)d_in[17];
    const float* ln0_b   = (const float*)d_in[18];
    const float* ln1_w   = (const float*)d_in[19];
    const float* ln1_b   = (const float*)d_in[20];
    const float* ln2_w   = (const float*)d_in[21];
    const float* ln2_b   = (const float*)d_in[22];
    const float* ffn_w   = (const float*)d_in[23];
    const float* ffn_b   = (const float*)d_in[24];
    const float* w1_w    = (const float*)d_in[25];
    const float* w1_b    = (const float*)d_in[26];
    const float* w2_w    = (const float*)d_in[27];
    const float* w2_b    = (const float*)d_in[28];
    float* out = (float*)d_out;

    __half* hs = nullptr;
    float* biasOW = nullptr;
    cudaGetSymbolAddress((void**)&hs, g_h);
    cudaGetSymbolAddress((void**)&biasOW, g_bias);
    __half* nq   = hs;                       // 3*CH (nq,nk,nv)
    __half* nk   = hs + CH;
    __half* nv   = hs + 2 * CH;
    __half* fx   = hs + 3 * CH;
    __half* q    = hs + 4 * CH;
    __half* k    = hs + 5 * CH;
    __half* v    = hs + 6 * CH;
    __half* yc   = hs + 7 * CH;              // [TOK, KC2]
    __half* wq_r = yc + (size_t)TOK * KC2;
    __half* wk_r = wq_r + WQKVO_SZ;
    __half* wv_r = wk_r + WQKVO_SZ;
    __half* w1_r = wv_r + WQKVO_SZ;
    __half* wow2 = w1_r + W12_SZ;            // [DMODEL, KC2]

    if (!g_side) {
        int lo = 0, hi = 0;
        cudaDeviceGetStreamPriorityRange(&lo, &hi);
        cudaStreamCreateWithPriority(&g_side, cudaStreamNonBlocking, lo);
        cudaStreamCreateWithFlags(&g_side2, cudaStreamNonBlocking);
        cudaStreamCreateWithFlags(&g_side3, cudaStreamNonBlocking);
        cudaEventCreateWithFlags(&g_ev0,  cudaEventDisableTiming);
        cudaEventCreateWithFlags(&g_evc,  cudaEventDisableTiming);
        cudaEventCreateWithFlags(&g_evln, cudaEventDisableTiming);
        cudaEventCreateWithFlags(&g_evj,  cudaEventDisableTiming);
        cudaEventCreateWithFlags(&g_evk,  cudaEventDisableTiming);
        cudaEventCreateWithFlags(&g_evrk, cudaEventDisableTiming);
        cudaEventCreateWithFlags(&g_evq,  cudaEventDisableTiming);
        cudaEventCreateWithFlags(&g_evrq, cudaEventDisableTiming);
        cudaEventCreateWithFlags(&g_evv,  cudaEventDisableTiming);
        cudaEventCreateWithFlags(&g_evA1, cudaEventDisableTiming);
        cudaEventCreateWithFlags(&g_evF1, cudaEventDisableTiming);
    }

    cudaFuncSetAttribute(gemm_h_kernel<ACT_NONE, false, true>,
                         cudaFuncAttributeMaxDynamicSharedMemorySize, GSMEM);
    cudaFuncSetAttribute(gemm_h_kernel<ACT_NONE, true, false>,
                         cudaFuncAttributeMaxDynamicSharedMemorySize, GSMEM);
    cudaFuncSetAttribute(gemm_h_kernel<ACT_GELU, false, true>,
                         cudaFuncAttributeMaxDynamicSharedMemorySize, GSMEM);
    cudaFuncSetAttribute(attn_h_kernel,
                         cudaFuncAttributeMaxDynamicSharedMemorySize, ASMEM);

    const int nw4 = (int)(WQKVO_SZ / 4), nh4 = (int)(W12_SZ / 4);

    // side: weight conversion + bias sum, overlapping main-stream layernorms
    cudaEventRecord(g_ev0, 0);
    cudaStreamWaitEvent(g_side, g_ev0, 0);
    round_h6_kernel<<<dim3((nh4 + 255) / 256, 6), 256, 0, g_side>>>(
        (const float4*)wq_w, (const float4*)wk_w, (const float4*)wv_w,
        (const float4*)wo_w, (const float4*)w1_w, (const float4*)w2_w,
        (uint2*)wq_r, (uint2*)wk_r, (uint2*)wv_r, wow2, (uint2*)w1_r,
        nw4, nh4);
    bias_sum_kernel<<<(DMODEL + 255) / 256, 256, 0, g_side>>>(wo_b, w2_b, biasOW);
    cudaEventRecord(g_evc, g_side);

    // main: fused layernorms
    layernorm4_kernel<<<dim3(TOK, 4), 256>>>(
        x0, x1, x2, x3,
        ln0_w, ln1_w, ln2_w, ffn_w,
        ln0_b, ln1_b, ln2_b, ffn_b,
        nq, nk, nv, fx);
    cudaEventRecord(g_evln, 0);

    // side (low priority): ffn1 -> yc cols [2048, 7936)
    cudaStreamWaitEvent(g_side, g_evln, 0);
    dim3 g1(HID / 256, TOK / 128, 1);
    gemm_h_kernel<ACT_GELU, false, true><<<g1, 256, GSMEM, g_side>>>(
        fx, w1_r, w1_b, nullptr, nullptr, nullptr, yc,
        TOK, HID, DMODEL, KC2, DMODEL, 0, 0, 0);
    cudaEventRecord(g_evj, g_side);

    // main: K projection (needs conv + LN)
    cudaStreamWaitEvent(0, g_evc, 0);
    dim3 gp(DMODEL / 256, TOK / 128, 1);
    gemm_h_kernel<ACT_NONE, false, true><<<gp, 256, GSMEM>>>(
        nk, wk_r, wk_b, nullptr, nullptr, nullptr, k,
        TOK, DMODEL, DMODEL, DMODEL, 0, 0, 0, 0);
    cudaEventRecord(g_evk, 0);

    // side2: rope-k concurrently with Q/V projections
    cudaStreamWaitEvent(g_side2, g_evk, 0);
    qknorm_rope_kernel<<<TOK, 256, 0, g_side2>>>(k, kn_w, freqs);
    cudaEventRecord(g_evrk, g_side2);

    // main: Q projection
    gemm_h_kernel<ACT_NONE, false, true><<<gp, 256, GSMEM>>>(
        nq, wq_r, wq_b, nullptr, nullptr, nullptr, q,
        TOK, DMODEL, DMODEL, DMODEL, 0, 0, 0, 0);
    cudaEventRecord(g_evq, 0);

    // side3: rope-q concurrently with V projection
    cudaStreamWaitEvent(g_side3, g_evq, 0);
    qknorm_rope_kernel<<<TOK, 256, 0, g_side3>>>(q, qn_w, freqs);
    cudaEventRecord(g_evrq, g_side3);

    // main: V projection
    gemm_h_kernel<ACT_NONE, false, true><<<gp, 256, GSMEM>>>(
        nv, wv_r, wv_b, nullptr, nullptr, nullptr, v,
        TOK, DMODEL, DMODEL, DMODEL, 0, 0, 0, 0);
    cudaEventRecord(g_evv, 0);

    // main: attention batch 0 (needs rope-q, rope-k, V)
    cudaStreamWaitEvent(0, g_evrk, 0);
    cudaStreamWaitEvent(0, g_evrq, 0);
    attn_h_kernel<<<dim3(SEQ / 64, NHEAD), 128, ASMEM>>>(q, k, v, yc, 0);

    // side2: attention batch 1, concurrent with batch 0
    cudaStreamWaitEvent(g_side2, g_evrq, 0);
    cudaStreamWaitEvent(g_side2, g_evv, 0);
    attn_h_kernel<<<dim3(SEQ / 64, NHEAD), 128, ASMEM, g_side2>>>(q, k, v, yc, 1);
    cudaEventRecord(g_evA1, g_side2);

    // main: fused O+FFN2 half 0 (rows 0..2047) after attn b0 (+ ffn1)
    cudaStreamWaitEvent(0, g_evj, 0);
    dim3 gf(DMODEL / 256, SEQ / 128, 1);
    gemm_h_kernel<ACT_NONE, true, false><<<gf, 256, GSMEM>>>(
        yc, wow2, biasOW, nullptr, nullptr, x3, out,
        SEQ, DMODEL, KC2, DMODEL, 0, 0, 0, 0);

    // side2: fused O+FFN2 half 1 after attn b1 (+ ffn1)
    cudaStreamWaitEvent(g_side2, g_evj, 0);
    gemm_h_kernel<ACT_NONE, true, false><<<gf, 256, GSMEM, g_side2>>>(
        yc + (size_t)SEQ * KC2, wow2, biasOW, nullptr, nullptr,
        x3 + (size_t)SEQ * DMODEL, out + (size_t)SEQ * DMODEL,
        SEQ, DMODEL, KC2, DMODEL, 0, 0, 0, 0);
    cudaEventRecord(g_evF1, g_side2);

    // join side2 into main so the captured graph covers fused half 1
    cudaStreamWaitEvent(0, g_evF1, 0);
}

// round 14
// speedup vs baseline: 1.0264x; 1.0264x over previous
#include <cuda_runtime.h>
#include <cuda_fp16.h>
#include <stdint.h>

#define BATCH 2
#define SEQ   2048
#define DMODEL 2048
#define NHEAD 16
#define HDIM  128
#define HID   5888
#define TOK   (BATCH*SEQ)            // 4096
#define CH    ((size_t)TOK*DMODEL)   // 8388608
#define KC2   7936                   // DMODEL + HID (fused O+FFN2 K dim)
#define EPSV  1e-5f
#define SCALE_ATT 0.08838834764831845f

#define WQKVO_SZ ((size_t)DMODEL*DMODEL)
#define W12_SZ   ((size_t)HID*DMODEL)
#define HTOT (7*CH + (size_t)TOK*KC2 + 3*WQKVO_SZ + W12_SZ + (size_t)DMODEL*KC2)

__device__ __half g_h[HTOT];
__device__ float g_bias[DMODEL];     // wo_b + w2_b

// ---------------- helpers ---------------------------------------------------
__device__ __forceinline__ uint32_t smem_u32(const void* p) {
    uint32_t a;
    asm("{ .reg .u64 t; cvta.to.shared.u64 t, %1; cvt.u32.u64 %0, t; }"
        : "=r"(a) : "l"(p));
    return a;
}
__device__ __forceinline__ uint32_t packh2(float a, float b) {
    __half2 h = __floats2half2_rn(a, b);
    return *(uint32_t*)&h;
}
__device__ __forceinline__ void cpasync16(uint32_t dst, const void* src) {
    asm volatile("cp.async.cg.shared.global [%0], [%1], 16;" :: "r"(dst), "l"(src) : "memory");
}
#define CP_COMMIT() asm volatile("cp.async.commit_group;" ::: "memory")
#define CP_WAIT2()  asm volatile("cp.async.wait_group 2;" ::: "memory")

#define LDSM4(r, addr) \
    asm volatile("ldmatrix.sync.aligned.m8n8.x4.shared.b16 {%0,%1,%2,%3}, [%4];" \
        : "=r"((r)[0]), "=r"((r)[1]), "=r"((r)[2]), "=r"((r)[3]) : "r"(addr))
#define LDSM4T(r, addr) \
    asm volatile("ldmatrix.sync.aligned.m8n8.x4.trans.shared.b16 {%0,%1,%2,%3}, [%4];" \
        : "=r"((r)[0]), "=r"((r)[1]), "=r"((r)[2]), "=r"((r)[3]) : "r"(addr))

__device__ __forceinline__ void mma_h(float (&c)[4], const uint32_t (&a)[4],
                                      uint32_t b0, uint32_t b1) {
    asm volatile(
        "mma.sync.aligned.m16n8k16.row.col.f32.f16.f16.f32 "
        "{%0,%1,%2,%3}, {%4,%5,%6,%7}, {%8,%9}, {%0,%1,%2,%3};\n"
        : "+f"(c[0]), "+f"(c[1]), "+f"(c[2]), "+f"(c[3])
        : "r"(a[0]), "r"(a[1]), "r"(a[2]), "r"(a[3]), "r"(b0), "r"(b1));
}

// ---------------- fused fp32 -> fp16 weight conversion ----------------------
// z: 0=wq 1=wk 2=wv 3=wo(->wow2 cols 0-2047) 4=w1 5=w2(->wow2 cols 2048+)
__global__ __launch_bounds__(256) void round_h6_kernel(
    const float4* __restrict__ s0, const float4* __restrict__ s1,
    const float4* __restrict__ s2, const float4* __restrict__ s3,
    const float4* __restrict__ s4, const float4* __restrict__ s5,
    uint2* __restrict__ d0, uint2* __restrict__ d1,
    uint2* __restrict__ d2, __half* __restrict__ dcw,
    uint2* __restrict__ d4,
    int nw4, int nh4)
{
    const int z = blockIdx.y;
    const int n4 = (z == 3 || z < 3) ? nw4 : nh4;
    const int i = blockIdx.x * 256 + threadIdx.x;
    if (i >= n4) return;
    const float4* in = (z == 0) ? s0 : (z == 1) ? s1 : (z == 2) ? s2
                     : (z == 3) ? s3 : (z == 4) ? s4 : s5;
    float4 v = in[i];
    uint2 u;
    u.x = packh2(v.x, v.y);
    u.y = packh2(v.z, v.w);
    if (z < 3) {
        uint2* out = (z == 0) ? d0 : (z == 1) ? d1 : d2;
        out[i] = u;
    } else if (z == 4) {
        d4[i] = u;
    } else if (z == 3) {
        const int e = i * 4;
        const int n = e >> 11, kk = e & 2047;
        *(uint2*)(dcw + (size_t)n * KC2 + kk) = u;
    } else {
        const int e = i * 4;
        const int n = e / HID, kk = e - n * HID;
        *(uint2*)(dcw + (size_t)n * KC2 + DMODEL + kk) = u;
    }
}

__global__ __launch_bounds__(256) void bias_sum_kernel(
    const float* __restrict__ a, const float* __restrict__ b,
    float* __restrict__ c)
{
    const int i = blockIdx.x * 256 + threadIdx.x;
    if (i < DMODEL) c[i] = a[i] + b[i];
}

// ---------------- fused layernorm x4 (fp32 in, fp16 out) --------------------
__global__ __launch_bounds__(256) void layernorm4_kernel(
    const float* __restrict__ x0, const float* __restrict__ x1,
    const float* __restrict__ x2, const float* __restrict__ x3,
    const float* __restrict__ w0, const float* __restrict__ w1,
    const float* __restrict__ w2, const float* __restrict__ w3,
    const float* __restrict__ b0p, const float* __restrict__ b1p,
    const float* __restrict__ b2p, const float* __restrict__ b3p,
    __half* __restrict__ o0p, __half* __restrict__ o1p,
    __half* __restrict__ o2p, __half* __restrict__ o3p)
{
    const int z = blockIdx.y;
    const float* x = (z == 0) ? x0 : (z == 1) ? x1 : (z == 2) ? x2 : x3;
    const float* w = (z == 0) ? w0 : (z == 1) ? w1 : (z == 2) ? w2 : w3;
    const float* b = (z == 0) ? b0p : (z == 1) ? b1p : (z == 2) ? b2p : b3p;
    __half* out    = (z == 0) ? o0p : (z == 1) ? o1p : (z == 2) ? o2p : o3p;

    const int row = blockIdx.x;
    const int t = threadIdx.x;
    const float4* xp = (const float4*)(x + (size_t)row * DMODEL);
    float4 v0 = xp[t], v1 = xp[t + 256];
    float s  = v0.x + v0.y + v0.z + v0.w + v1.x + v1.y + v1.z + v1.w;
    float ss = v0.x*v0.x + v0.y*v0.y + v0.z*v0.z + v0.w*v0.w
             + v1.x*v1.x + v1.y*v1.y + v1.z*v1.z + v1.w*v1.w;
    __shared__ float sred[16];
    const int lane = t & 31, warp = t >> 5;
#pragma unroll
    for (int o = 16; o; o >>= 1) {
        s  += __shfl_xor_sync(0xffffffffu, s,  o);
        ss += __shfl_xor_sync(0xffffffffu, ss, o);
    }
    if (lane == 0) { sred[warp] = s; sred[8 + warp] = ss; }
    __syncthreads();
    if (t < 32) {
        s  = (t < 8) ? sred[t]     : 0.f;
        ss = (t < 8) ? sred[8 + t] : 0.f;
#pragma unroll
        for (int o = 4; o; o >>= 1) {
            s  += __shfl_xor_sync(0xffffffffu, s,  o);
            ss += __shfl_xor_sync(0xffffffffu, ss, o);
        }
        if (t == 0) { sred[0] = s; sred[1] = ss; }
    }
    __syncthreads();
    const float mean = sred[0] * (1.f / DMODEL);
    const float var  = sred[1] * (1.f / DMODEL) - mean * mean;
    const float inv  = rsqrtf(var + EPSV);
    const float4* wp = (const float4*)w;
    const float4* bp = (const float4*)b;
    float4 wv0 = wp[t], wv1 = wp[t + 256], bv0 = bp[t], bv1 = bp[t + 256];
    uint2 u0, u1;
    u0.x = packh2((v0.x - mean) * inv * wv0.x + bv0.x, (v0.y - mean) * inv * wv0.y + bv0.y);
    u0.y = packh2((v0.z - mean) * inv * wv0.z + bv0.z, (v0.w - mean) * inv * wv0.w + bv0.w);
    u1.x = packh2((v1.x - mean) * inv * wv1.x + bv1.x, (v1.y - mean) * inv * wv1.y + bv1.y);
    u1.y = packh2((v1.z - mean) * inv * wv1.z + bv1.z, (v1.w - mean) * inv * wv1.w + bv1.w);
    uint2* op = (uint2*)(out + (size_t)row * DMODEL);
    op[t] = u0;
    op[t + 256] = u1;
}

// ------- pipelined fp16 mma GEMM: C[., c_off + 0..N) = A[M,K] @ Bw[N,K]^T ---
#define ACT_NONE 0
#define ACT_GELU 1
#define GSTAGE 49152
#define GSMEM  (4 * GSTAGE)     // 192 KB

template <int ACT, bool RES, bool OUTH>
__global__ __launch_bounds__(256, 1) void gemm_h_kernel(
    const __half* __restrict__ A, const __half* __restrict__ Bw,
    const float* __restrict__ bias0, const float* __restrict__ bias1,
    const float* __restrict__ bias2, const float* __restrict__ Resid,
    void* __restrict__ Cv, int M, int N, int K, int ldC, int c_off,
    size_t aZ, size_t wZ, size_t cZ)
{
    extern __shared__ char smem[];
    const uint32_t s0 = smem_u32(smem);
    const int tid = threadIdx.x;
    const int warp = tid >> 5, lane = tid & 31;
    const int wm = (warp & 1) << 6;
    const int wn = (warp >> 1) << 6;
    const int l15 = lane & 15, lh = lane >> 4;
    const int z = blockIdx.z;
    const float* bias = (z == 0) ? bias0 : (z == 1) ? bias1 : bias2;
    const __half* Ab = A  + (size_t)z * aZ + (size_t)(blockIdx.y * 128) * K;
    const __half* Bb = Bw + (size_t)z * wZ + (size_t)(blockIdx.x * 256) * K;
    const int nk = K >> 6;

#define G_LOAD(kt)                                                            \
    {                                                                         \
        const int st_ = (kt) & 3;                                             \
        const uint32_t sA_ = s0 + st_ * GSTAGE;                               \
        const uint32_t sB_ = sA_ + 16384;                                     \
        const size_t kof_ = (size_t)(kt) * 64;                                \
        _Pragma("unroll")                                                     \
        for (int p = 0; p < 4; ++p) {                                         \
            const int cid = tid + (p << 8);                                   \
            const int row = cid >> 3, c4 = cid & 7;                           \
            const uint32_t sw = row * 128 + ((c4 ^ (row & 7)) << 4);          \
            cpasync16(sA_ + sw, Ab + (size_t)row * K + kof_ + c4 * 8);        \
        }                                                                     \
        _Pragma("unroll")                                                     \
        for (int p = 0; p < 8; ++p) {                                         \
            const int cid = tid + (p << 8);                                   \
            const int row = cid >> 3, c4 = cid & 7;                           \
            const uint32_t sw = row * 128 + ((c4 ^ (row & 7)) << 4);          \
            cpasync16(sB_ + sw, Bb + (size_t)row * K + kof_ + c4 * 8);        \
        }                                                                     \
    }

    G_LOAD(0); CP_COMMIT();
    G_LOAD(1); CP_COMMIT();
    G_LOAD(2); CP_COMMIT();

    float acc[4][8][4];
#pragma unroll
    for (int i = 0; i < 4; i++)
#pragma unroll
        for (int j = 0; j < 8; j++)
#pragma unroll
            for (int r = 0; r < 4; r++) acc[i][j][r] = 0.f;

    for (int kt = 0; kt < nk; ++kt) {
        CP_WAIT2();
        __syncthreads();
        if (kt + 3 < nk) G_LOAD(kt + 3);
        CP_COMMIT();

        const uint32_t sA = s0 + (kt & 3) * GSTAGE, sB = sA + 16384;
#pragma unroll
        for (int kk = 0; kk < 4; ++kk) {
            uint32_t af[4][4], bf[4][4];
            const int ch = (kk << 1) + lh;
#pragma unroll
            for (int i = 0; i < 4; ++i) {
                const int row = wm + i * 16 + l15;
                LDSM4(af[i], sA + row * 128 + ((ch ^ (row & 7)) << 4));
            }
#pragma unroll
            for (int jp = 0; jp < 4; ++jp) {
                const int row = wn + jp * 16 + l15;
                LDSM4(bf[jp], sB + row * 128 + ((ch ^ (row & 7)) << 4));
            }
#pragma unroll
            for (int i = 0; i < 4; ++i)
#pragma unroll
                for (int jp = 0; jp < 4; ++jp) {
                    mma_h(acc[i][2*jp],   af[i], bf[jp][0], bf[jp][2]);
                    mma_h(acc[i][2*jp+1], af[i], bf[jp][1], bf[jp][3]);
                }
        }
    }
#undef G_LOAD

    const int g = lane >> 2, tg = lane & 3;
    const int rowbase = blockIdx.y * 128 + wm;
    const int colbase = blockIdx.x * 256 + wn;
#pragma unroll
    for (int i = 0; i < 4; ++i) {
#pragma unroll
        for (int j = 0; j < 8; ++j) {
            const int r0 = rowbase + i * 16 + g;
            const int c0 = colbase + j * 8 + tg * 2;
            const float bia0 = bias[c0], bia1 = bias[c0 + 1];
#pragma unroll
            for (int hr = 0; hr < 2; ++hr) {
                const int row = r0 + hr * 8;
                float v0 = acc[i][j][hr * 2 + 0] + bia0;
                float v1 = acc[i][j][hr * 2 + 1] + bia1;
                if (RES) {
                    v0 += Resid[(size_t)row * N + c0];
                    v1 += Resid[(size_t)row * N + c0 + 1];
                }
                if (ACT == ACT_GELU) {
                    v0 = 0.5f * v0 * (1.f + erff(v0 * 0.7071067811865475f));
                    v1 = 0.5f * v1 * (1.f + erff(v1 * 0.7071067811865475f));
                }
                if (OUTH) {
                    __half* Cb = (__half*)Cv + (size_t)z * cZ;
                    *(uint32_t*)&Cb[(size_t)row * ldC + c_off + c0] = packh2(v0, v1);
                } else {
                    float* Cb = (float*)Cv + (size_t)z * cZ;
                    *(float2*)&Cb[(size_t)row * ldC + c_off + c0] = make_float2(v0, v1);
                }
            }
        }
    }
}

// ---------------- per-head rmsnorm + rope (fp16 in-place, single tensor) ----
__global__ __launch_bounds__(256) void qknorm_rope_kernel(
    __half* __restrict__ x, const float* __restrict__ w,
    const float* __restrict__ freqs)
{
    const int token = blockIdx.x;
    const int pos = token & (SEQ - 1);
    const int warp = threadIdx.x >> 5, lane = threadIdx.x & 31;
    __shared__ float rb[8][32];
    const float4 wv = ((const float4*)w)[lane];
#pragma unroll
    for (int hh = 0; hh < 2; hh++) {
        const int h = warp + hh * 8;
        __half* p = x + (size_t)token * DMODEL + h * HDIM;
        uint2 raw = ((uint2*)p)[lane];
        const __half2 h0 = *(__half2*)&raw.x, h1 = *(__half2*)&raw.y;
        float v0 = __low2float(h0), v1 = __high2float(h0);
        float v2 = __low2float(h1), v3 = __high2float(h1);
        float ssq = v0*v0 + v1*v1 + v2*v2 + v3*v3;
#pragma unroll
        for (int o = 16; o; o >>= 1) ssq += __shfl_xor_sync(0xffffffffu, ssq, o);
        const float inv = rsqrtf(ssq * (1.f / HDIM) + EPSV);
        float o0 = v0 * inv * wv.x, o1 = v1 * inv * wv.y;
        float o2 = v2 * inv * wv.z, o3 = v3 * inv * wv.w;
        const int d0 = lane * 4;
        if (d0 < 32) {
            rb[warp][d0] = o0; rb[warp][d0 + 1] = o1;
            rb[warp][d0 + 2] = o2; rb[warp][d0 + 3] = o3;
        }
        __syncwarp();
        if (d0 < 32) {
            float r[4];
#pragma unroll
            for (int i = 0; i < 4; i++) {
                const int d = d0 + i, ii = d >> 1;
                const float x1 = rb[warp][ii], x2 = rb[warp][ii + 16];
                const float c  = freqs[pos * 32 + ii * 2];
                const float sn = freqs[pos * 32 + ii * 2 + 1];
                r[i] = (d & 1) ? (x2 * c + x1 * sn) : (x1 * c - x2 * sn);
            }
            o0 = r[0]; o1 = r[1]; o2 = r[2]; o3 = r[3];
        }
        __syncwarp();
        raw.x = packh2(o0, o1);
        raw.y = packh2(o2, o3);
        ((uint2*)p)[lane] = raw;
    }
}

// ---------------- causal flash attention (fp16 mma), per-batch --------------
#define ASTAGE 16384
#define ASMEM  (4 * ASTAGE)

__global__ __launch_bounds__(128, 3) void attn_h_kernel(
    const __half* __restrict__ Q, const __half* __restrict__ Kx,
    const __half* __restrict__ Vx, __half* __restrict__ O, int b)
{
    extern __shared__ char smem[];
    const uint32_t s0 = smem_u32(smem);
    const int tid = threadIdx.x;
    const int warp = tid >> 5, lane = tid & 31;
    const int g = lane >> 2, tg = lane & 3;
    const int l15 = lane & 15, lh = lane >> 4;
    const int qb = gridDim.x - 1 - blockIdx.x;
    const int h = blockIdx.y;
    const size_t base = ((size_t)b * SEQ) * DMODEL + h * HDIM;
    const size_t obase = ((size_t)b * SEQ) * KC2 + h * HDIM;
    const int q0 = qb * 64;
    const int wq = warp * 16;
    const int nkt = (q0 >> 5) + 2;
    const int r0 = q0 + wq + g, r1 = r0 + 8;

    uint32_t aq[8][4];
    {
        const __half* q_r0 = Q + base + (size_t)r0 * DMODEL;
        const __half* q_r1 = q_r0 + (size_t)8 * DMODEL;
#pragma unroll
        for (int kk = 0; kk < 8; ++kk) {
            aq[kk][0] = *(const uint32_t*)(q_r0 + kk * 16 + tg * 2);
            aq[kk][1] = *(const uint32_t*)(q_r1 + kk * 16 + tg * 2);
            aq[kk][2] = *(const uint32_t*)(q_r0 + kk * 16 + 8 + tg * 2);
            aq[kk][3] = *(const uint32_t*)(q_r1 + kk * 16 + 8 + tg * 2);
        }
    }

#define A_LOAD(kt)                                                            \
    {                                                                         \
        const int st_ = (kt) & 3;                                             \
        const uint32_t Kst_ = s0 + st_ * ASTAGE;                              \
        const uint32_t Vst_ = Kst_ + 8192;                                    \
        const int kv0_ = (kt) << 5;                                           \
        _Pragma("unroll")                                                     \
        for (int p = 0; p < 4; ++p) {                                         \
            const int cid = tid + (p << 7);                                   \
            const int row = cid >> 4, c = cid & 15;                           \
            const uint32_t sw = row * 256 + ((c ^ (row & 7)) << 4);           \
            const size_t go = base + (size_t)(kv0_ + row) * DMODEL + c * 8;   \
            cpasync16(Kst_ + sw, Kx + go);                                    \
            cpasync16(Vst_ + sw, Vx + go);                                    \
        }                                                                     \
    }

    A_LOAD(0); CP_COMMIT();
    A_LOAD(1); CP_COMMIT();
    A_LOAD(2); CP_COMMIT();

    float m0 = -1e30f, m1 = -1e30f, l0 = 0.f, l1 = 0.f;
    float o[16][4];
#pragma unroll
    for (int nb = 0; nb < 16; ++nb)
#pragma unroll
        for (int r = 0; r < 4; ++r) o[nb][r] = 0.f;

    for (int kt = 0; kt < nkt; ++kt) {
        CP_WAIT2();
        __syncthreads();
        if (kt + 3 < nkt) A_LOAD(kt + 3);
        CP_COMMIT();

        const int kv0 = kt << 5;
        if (kv0 <= q0 + wq + 15) {
            const uint32_t Kst = s0 + (kt & 3) * ASTAGE;
            const uint32_t Vst = Kst + 8192;

            float sc[4][4];
#pragma unroll
            for (int jb = 0; jb < 4; ++jb)
#pragma unroll
                for (int r = 0; r < 4; ++r) sc[jb][r] = 0.f;
#pragma unroll
            for (int kk = 0; kk < 8; ++kk) {
                const int ch = (kk << 1) + lh;
#pragma unroll
                for (int jp = 0; jp < 2; ++jp) {
                    uint32_t bf[4];
                    const int row = jp * 16 + l15;
                    LDSM4(bf, Kst + row * 256 + ((ch ^ (row & 7)) << 4));
                    mma_h(sc[2*jp],   aq[kk], bf[0], bf[2]);
                    mma_h(sc[2*jp+1], aq[kk], bf[1], bf[3]);
                }
            }

            const bool diag = (kv0 + 31 > r0) || (kv0 + 31 > r1);
#pragma unroll
            for (int jb = 0; jb < 4; ++jb) {
                const int c0 = kv0 + jb * 8 + tg * 2;
                sc[jb][0] *= SCALE_ATT; sc[jb][1] *= SCALE_ATT;
                sc[jb][2] *= SCALE_ATT; sc[jb][3] *= SCALE_ATT;
                if (diag) {
                    if (c0     > r0) sc[jb][0] = -1e30f;
                    if (c0 + 1 > r0) sc[jb][1] = -1e30f;
                    if (c0     > r1) sc[jb][2] = -1e30f;
                    if (c0 + 1 > r1) sc[jb][3] = -1e30f;
                }
            }

            float rm0 = sc[0][0], rm1 = sc[0][2];
#pragma unroll
            for (int jb = 0; jb < 4; ++jb) {
                rm0 = fmaxf(rm0, fmaxf(sc[jb][0], sc[jb][1]));
                rm1 = fmaxf(rm1, fmaxf(sc[jb][2], sc[jb][3]));
            }
            rm0 = fmaxf(rm0, __shfl_xor_sync(0xffffffffu, rm0, 1));
            rm0 = fmaxf(rm0, __shfl_xor_sync(0xffffffffu, rm0, 2));
            rm1 = fmaxf(rm1, __shfl_xor_sync(0xffffffffu, rm1, 1));
            rm1 = fmaxf(rm1, __shfl_xor_sync(0xffffffffu, rm1, 2));
            const float mx0 = fmaxf(m0, rm0), mx1 = fmaxf(m1, rm1);
            const float corr0 = __expf(m0 - mx0), corr1 = __expf(m1 - mx1);
            float rs0 = 0.f, rs1 = 0.f;
#pragma unroll
            for (int jb = 0; jb < 4; ++jb) {
                sc[jb][0] = __expf(sc[jb][0] - mx0);
                sc[jb][1] = __expf(sc[jb][1] - mx0);
                sc[jb][2] = __expf(sc[jb][2] - mx1);
                sc[jb][3] = __expf(sc[jb][3] - mx1);
                rs0 += sc[jb][0] + sc[jb][1];
                rs1 += sc[jb][2] + sc[jb][3];
            }
            rs0 += __shfl_xor_sync(0xffffffffu, rs0, 1);
            rs0 += __shfl_xor_sync(0xffffffffu, rs0, 2);
            rs1 += __shfl_xor_sync(0xffffffffu, rs1, 1);
            rs1 += __shfl_xor_sync(0xffffffffu, rs1, 2);
            l0 = l0 * corr0 + rs0;  m0 = mx0;
            l1 = l1 * corr1 + rs1;  m1 = mx1;
#pragma unroll
            for (int nb = 0; nb < 16; ++nb) {
                o[nb][0] *= corr0; o[nb][1] *= corr0;
                o[nb][2] *= corr1; o[nb][3] *= corr1;
            }

#pragma unroll
            for (int kc = 0; kc < 2; ++kc) {
                uint32_t pa[4];
                pa[0] = packh2(sc[2*kc][0],   sc[2*kc][1]);
                pa[1] = packh2(sc[2*kc][2],   sc[2*kc][3]);
                pa[2] = packh2(sc[2*kc+1][0], sc[2*kc+1][1]);
                pa[3] = packh2(sc[2*kc+1][2], sc[2*kc+1][3]);
#pragma unroll
                for (int cp = 0; cp < 8; ++cp) {
                    uint32_t vf[4];
                    const int row = kc * 16 + l15;
                    const int ch = (cp << 1) + lh;
                    LDSM4T(vf, Vst + row * 256 + ((ch ^ (row & 7)) << 4));
                    mma_h(o[2*cp],   pa, vf[0], vf[1]);
                    mma_h(o[2*cp+1], pa, vf[2], vf[3]);
                }
            }
        }
    }
#undef A_LOAD

    const float inv0 = 1.f / l0, inv1 = 1.f / l1;
    __half* o_r0 = O + obase + (size_t)r0 * KC2;
    __half* o_r1 = O + obase + (size_t)r1 * KC2;
#pragma unroll
    for (int nb = 0; nb < 16; ++nb) {
        const int c = nb * 8 + tg * 2;
        *(uint32_t*)&o_r0[c] = packh2(o[nb][0] * inv0, o[nb][1] * inv0);
        *(uint32_t*)&o_r1[c] = packh2(o[nb][2] * inv1, o[nb][3] * inv1);
    }
}

// ---------------- launcher --------------------------------------------------
static cudaStream_t g_side = nullptr, g_side2 = nullptr;
static cudaEvent_t g_ev0 = nullptr, g_evc = nullptr, g_evln = nullptr,
                   g_evj = nullptr, g_evk = nullptr, g_evrk = nullptr,
                   g_evrq = nullptr, g_evF1 = nullptr;

extern "C" void kernel_launch(void* const* d_in, const int* in_sizes, int n_in,
                              void* d_out, int out_size)
{
    const float* x0      = (const float*)d_in[0];
    const float* x1      = (const float*)d_in[1];
    const float* x2      = (const float*)d_in[2];
    const float* x3      = (const float*)d_in[3];
    const float* freqs   = (const float*)d_in[5];
    const float* wq_w    = (const float*)d_in[7];
    const float* wq_b    = (const float*)d_in[8];
    const float* wk_w    = (const float*)d_in[9];
    const float* wk_b    = (const float*)d_in[10];
    const float* wv_w    = (const float*)d_in[11];
    const float* wv_b    = (const float*)d_in[12];
    const float* wo_w    = (const float*)d_in[13];
    const float* wo_b    = (const float*)d_in[14];
    const float* qn_w    = (const float*)d_in[15];
    const float* kn_w    = (const float*)d_in[16];
    const float* ln0_w   = (const float*)d_in[17];
    const float* ln0_b   = (const float*)d_in[18];
    const float* ln1_w   = (const float*)d_in[19];
    const float* ln1_b   = (const float*)d_in[20];
    const float* ln2_w   = (const float*)d_in[21];
    const float* ln2_b   = (const float*)d_in[22];
    const float* ffn_w   = (const float*)d_in[23];
    const float* ffn_b   = (const float*)d_in[24];
    const float* w1_w    = (const float*)d_in[25];
    const float* w1_b    = (const float*)d_in[26];
    const float* w2_w    = (const float*)d_in[27];
    const float* w2_b    = (const float*)d_in[28];
    float* out = (float*)d_out;

    __half* hs = nullptr;
    float* biasOW = nullptr;
    cudaGetSymbolAddress((void**)&hs, g_h);
    cudaGetSymbolAddress((void**)&biasOW, g_bias);
    __half* nq   = hs;                       // 3*CH (nq,nk,nv)
    __half* nk   = hs + CH;
    __half* fx   = hs + 3 * CH;
    __half* q    = hs + 4 * CH;
    __half* k    = hs + 5 * CH;
    __half* v    = hs + 6 * CH;
    __half* yc   = hs + 7 * CH;              // [TOK, KC2]
    __half* wq_r = yc + (size_t)TOK * KC2;
    __half* wk_r = wq_r + WQKVO_SZ;
    __half* wv_r = wk_r + WQKVO_SZ;
    __half* w1_r = wv_r + WQKVO_SZ;
    __half* wow2 = w1_r + W12_SZ;            // [DMODEL, KC2]

    if (!g_side) {
        int lo = 0, hi = 0;
        cudaDeviceGetStreamPriorityRange(&lo, &hi);
        cudaStreamCreateWithPriority(&g_side, cudaStreamNonBlocking, lo);
        cudaStreamCreateWithFlags(&g_side2, cudaStreamNonBlocking);
        cudaEventCreateWithFlags(&g_ev0,  cudaEventDisableTiming);
        cudaEventCreateWithFlags(&g_evc,  cudaEventDisableTiming);
        cudaEventCreateWithFlags(&g_evln, cudaEventDisableTiming);
        cudaEventCreateWithFlags(&g_evj,  cudaEventDisableTiming);
        cudaEventCreateWithFlags(&g_evk,  cudaEventDisableTiming);
        cudaEventCreateWithFlags(&g_evrk, cudaEventDisableTiming);
        cudaEventCreateWithFlags(&g_evrq, cudaEventDisableTiming);
        cudaEventCreateWithFlags(&g_evF1, cudaEventDisableTiming);
    }

    cudaFuncSetAttribute(gemm_h_kernel<ACT_NONE, false, true>,
                         cudaFuncAttributeMaxDynamicSharedMemorySize, GSMEM);
    cudaFuncSetAttribute(gemm_h_kernel<ACT_NONE, true, false>,
                         cudaFuncAttributeMaxDynamicSharedMemorySize, GSMEM);
    cudaFuncSetAttribute(gemm_h_kernel<ACT_GELU, false, true>,
                         cudaFuncAttributeMaxDynamicSharedMemorySize, GSMEM);
    cudaFuncSetAttribute(attn_h_kernel,
                         cudaFuncAttributeMaxDynamicSharedMemorySize, ASMEM);

    const int nw4 = (int)(WQKVO_SZ / 4), nh4 = (int)(W12_SZ / 4);

    // side: weight conversion + bias sum, overlapping main-stream layernorms
    cudaEventRecord(g_ev0, 0);
    cudaStreamWaitEvent(g_side, g_ev0, 0);
    round_h6_kernel<<<dim3((nh4 + 255) / 256, 6), 256, 0, g_side>>>(
        (const float4*)wq_w, (const float4*)wk_w, (const float4*)wv_w,
        (const float4*)wo_w, (const float4*)w1_w, (const float4*)w2_w,
        (uint2*)wq_r, (uint2*)wk_r, (uint2*)wv_r, wow2, (uint2*)w1_r,
        nw4, nh4);
    bias_sum_kernel<<<(DMODEL + 255) / 256, 256, 0, g_side>>>(wo_b, w2_b, biasOW);
    cudaEventRecord(g_evc, g_side);

    // main: fused layernorms
    layernorm4_kernel<<<dim3(TOK, 4), 256>>>(
        x0, x1, x2, x3,
        ln0_w, ln1_w, ln2_w, ffn_w,
        ln0_b, ln1_b, ln2_b, ffn_b,
        nq, nq + CH, nq + 2 * CH, fx);
    cudaEventRecord(g_evln, 0);

    // side (low priority): ffn1 -> yc cols [2048, 7936)
    cudaStreamWaitEvent(g_side, g_evln, 0);
    dim3 g1(HID / 256, TOK / 128, 1);
    gemm_h_kernel<ACT_GELU, false, true><<<g1, 256, GSMEM, g_side>>>(
        fx, w1_r, w1_b, nullptr, nullptr, nullptr, yc,
        TOK, HID, DMODEL, KC2, DMODEL, 0, 0, 0);
    cudaEventRecord(g_evj, g_side);

    // main: K projection first (needs conv + LN)
    cudaStreamWaitEvent(0, g_evc, 0);
    dim3 gk(DMODEL / 256, TOK / 128, 1);
    gemm_h_kernel<ACT_NONE, false, true><<<gk, 256, GSMEM>>>(
        nk, wk_r, wk_b, nullptr, nullptr, nullptr, k,
        TOK, DMODEL, DMODEL, DMODEL, 0, 0, 0, 0);
    cudaEventRecord(g_evk, 0);

    // side2: rope-k concurrently with Q/V projection
    cudaStreamWaitEvent(g_side2, g_evk, 0);
    qknorm_rope_kernel<<<TOK, 256, 0, g_side2>>>(k, kn_w, freqs);
    cudaEventRecord(g_evrk, g_side2);

    // main: Q + V projection (z: 0->q, 1->v via 2x strides)
    dim3 gqv(DMODEL / 256, TOK / 128, 2);
    gemm_h_kernel<ACT_NONE, false, true><<<gqv, 256, GSMEM>>>(
        nq, wq_r, wq_b, wv_b, nullptr, nullptr, q,
        TOK, DMODEL, DMODEL, DMODEL, 0, 2 * CH, 2 * WQKVO_SZ, 2 * CH);

    // main: rope-q
    qknorm_rope_kernel<<<TOK, 256>>>(q, qn_w, freqs);
    cudaEventRecord(g_evrq, 0);

    // main: attention batch 0 (needs rope-k from side2)
    cudaStreamWaitEvent(0, g_evrk, 0);
    attn_h_kernel<<<dim3(SEQ / 64, NHEAD), 128, ASMEM>>>(q, k, v, yc, 0);

    // side2: attention batch 1, concurrent with batch 0 (rope-k in-order on
    // side2; rope-q via event)
    cudaStreamWaitEvent(g_side2, g_evrq, 0);
    attn_h_kernel<<<dim3(SEQ / 64, NHEAD), 128, ASMEM, g_side2>>>(q, k, v, yc, 1);

    // main: fused O+FFN2 half 0 (rows 0..2047) after attn b0 (+ ffn1)
    cudaStreamWaitEvent(0, g_evj, 0);
    dim3 gf(DMODEL / 256, SEQ / 128, 1);
    gemm_h_kernel<ACT_NONE, true, false><<<gf, 256, GSMEM>>>(
        yc, wow2, biasOW, nullptr, nullptr, x3, out,
        SEQ, DMODEL, KC2, DMODEL, 0, 0, 0, 0);

    // side2: fused O+FFN2 half 1 after attn b1 (+ ffn1)
    cudaStreamWaitEvent(g_side2, g_evj, 0);
    gemm_h_kernel<ACT_NONE, true, false><<<gf, 256, GSMEM, g_side2>>>(
        yc + (size_t)SEQ * KC2, wow2, biasOW, nullptr, nullptr,
        x3 + (size_t)SEQ * DMODEL, out + (size_t)SEQ * DMODEL,
        SEQ, DMODEL, KC2, DMODEL, 0, 0, 0, 0);
    cudaEventRecord(g_evF1, g_side2);

    // join side2 into main so the captured graph covers fused half 1
    cudaStreamWaitEvent(0, g_evF1, 0);
}

// round 15
// speedup vs baseline: 1.0453x; 1.0185x over previous
#include <cuda_runtime.h>
#include <cuda_fp16.h>
#include <stdint.h>

#define BATCH 2
#define SEQ   2048
#define DMODEL 2048
#define NHEAD 16
#define HDIM  128
#define HID   5888
#define TOK   (BATCH*SEQ)            // 4096
#define CH    ((size_t)TOK*DMODEL)   // 8388608
#define KC2   7936                   // DMODEL + HID (fused O+FFN2 K dim)
#define EPSV  1e-5f
#define SCALE_ATT 0.08838834764831845f

#define WQKVO_SZ ((size_t)DMODEL*DMODEL)
#define W12_SZ   ((size_t)HID*DMODEL)
#define HTOT (7*CH + (size_t)TOK*KC2 + 3*WQKVO_SZ + W12_SZ + (size_t)DMODEL*KC2)

__device__ __half g_h[HTOT];
__device__ float g_bias[DMODEL];     // wo_b + w2_b

// ---------------- helpers ---------------------------------------------------
__device__ __forceinline__ uint32_t smem_u32(const void* p) {
    uint32_t a;
    asm("{ .reg .u64 t; cvta.to.shared.u64 t, %1; cvt.u32.u64 %0, t; }"
        : "=r"(a) : "l"(p));
    return a;
}
__device__ __forceinline__ uint32_t packh2(float a, float b) {
    __half2 h = __floats2half2_rn(a, b);
    return *(uint32_t*)&h;
}
__device__ __forceinline__ void cpasync16(uint32_t dst, const void* src) {
    asm volatile("cp.async.cg.shared.global [%0], [%1], 16;" :: "r"(dst), "l"(src) : "memory");
}
#define CP_COMMIT() asm volatile("cp.async.commit_group;" ::: "memory")
#define CP_WAIT2()  asm volatile("cp.async.wait_group 2;" ::: "memory")

#define LDSM4(r, addr) \
    asm volatile("ldmatrix.sync.aligned.m8n8.x4.shared.b16 {%0,%1,%2,%3}, [%4];" \
        : "=r"((r)[0]), "=r"((r)[1]), "=r"((r)[2]), "=r"((r)[3]) : "r"(addr))
#define LDSM4T(r, addr) \
    asm volatile("ldmatrix.sync.aligned.m8n8.x4.trans.shared.b16 {%0,%1,%2,%3}, [%4];" \
        : "=r"((r)[0]), "=r"((r)[1]), "=r"((r)[2]), "=r"((r)[3]) : "r"(addr))

__device__ __forceinline__ void mma_h(float (&c)[4], const uint32_t (&a)[4],
                                      uint32_t b0, uint32_t b1) {
    asm volatile(
        "mma.sync.aligned.m16n8k16.row.col.f32.f16.f16.f32 "
        "{%0,%1,%2,%3}, {%4,%5,%6,%7}, {%8,%9}, {%0,%1,%2,%3};\n"
        : "+f"(c[0]), "+f"(c[1]), "+f"(c[2]), "+f"(c[3])
        : "r"(a[0]), "r"(a[1]), "r"(a[2]), "r"(a[3]), "r"(b0), "r"(b1));
}

// ---------------- fused fp32 -> fp16 weight conversion ----------------------
// z: 0=wq 1=wk 2=wv 3=wo(->wow2 cols 0-2047) 4=w1 5=w2(->wow2 cols 2048+)
__global__ __launch_bounds__(256) void round_h6_kernel(
    const float4* __restrict__ s0, const float4* __restrict__ s1,
    const float4* __restrict__ s2, const float4* __restrict__ s3,
    const float4* __restrict__ s4, const float4* __restrict__ s5,
    uint2* __restrict__ d0, uint2* __restrict__ d1,
    uint2* __restrict__ d2, __half* __restrict__ dcw,
    uint2* __restrict__ d4,
    int nw4, int nh4)
{
    const int z = blockIdx.y;
    const int n4 = (z == 3 || z < 3) ? nw4 : nh4;
    const int i = blockIdx.x * 256 + threadIdx.x;
    if (i >= n4) return;
    const float4* in = (z == 0) ? s0 : (z == 1) ? s1 : (z == 2) ? s2
                     : (z == 3) ? s3 : (z == 4) ? s4 : s5;
    float4 v = in[i];
    uint2 u;
    u.x = packh2(v.x, v.y);
    u.y = packh2(v.z, v.w);
    if (z < 3) {
        uint2* out = (z == 0) ? d0 : (z == 1) ? d1 : d2;
        out[i] = u;
    } else if (z == 4) {
        d4[i] = u;
    } else if (z == 3) {
        const int e = i * 4;
        const int n = e >> 11, kk = e & 2047;
        *(uint2*)(dcw + (size_t)n * KC2 + kk) = u;
    } else {
        const int e = i * 4;
        const int n = e / HID, kk = e - n * HID;
        *(uint2*)(dcw + (size_t)n * KC2 + DMODEL + kk) = u;
    }
}

__global__ __launch_bounds__(256) void bias_sum_kernel(
    const float* __restrict__ a, const float* __restrict__ b,
    float* __restrict__ c)
{
    const int i = blockIdx.x * 256 + threadIdx.x;
    if (i < DMODEL) c[i] = a[i] + b[i];
}

// ---------------- fused layernorm x4 (fp32 in, fp16 out) --------------------
__global__ __launch_bounds__(256) void layernorm4_kernel(
    const float* __restrict__ x0, const float* __restrict__ x1,
    const float* __restrict__ x2, const float* __restrict__ x3,
    const float* __restrict__ w0, const float* __restrict__ w1,
    const float* __restrict__ w2, const float* __restrict__ w3,
    const float* __restrict__ b0p, const float* __restrict__ b1p,
    const float* __restrict__ b2p, const float* __restrict__ b3p,
    __half* __restrict__ o0p, __half* __restrict__ o1p,
    __half* __restrict__ o2p, __half* __restrict__ o3p)
{
    const int z = blockIdx.y;
    const float* x = (z == 0) ? x0 : (z == 1) ? x1 : (z == 2) ? x2 : x3;
    const float* w = (z == 0) ? w0 : (z == 1) ? w1 : (z == 2) ? w2 : w3;
    const float* b = (z == 0) ? b0p : (z == 1) ? b1p : (z == 2) ? b2p : b3p;
    __half* out    = (z == 0) ? o0p : (z == 1) ? o1p : (z == 2) ? o2p : o3p;

    const int row = blockIdx.x;
    const int t = threadIdx.x;
    const float4* xp = (const float4*)(x + (size_t)row * DMODEL);
    float4 v0 = xp[t], v1 = xp[t + 256];
    float s  = v0.x + v0.y + v0.z + v0.w + v1.x + v1.y + v1.z + v1.w;
    float ss = v0.x*v0.x + v0.y*v0.y + v0.z*v0.z + v0.w*v0.w
             + v1.x*v1.x + v1.y*v1.y + v1.z*v1.z + v1.w*v1.w;
    __shared__ float sred[16];
    const int lane = t & 31, warp = t >> 5;
#pragma unroll
    for (int o = 16; o; o >>= 1) {
        s  += __shfl_xor_sync(0xffffffffu, s,  o);
        ss += __shfl_xor_sync(0xffffffffu, ss, o);
    }
    if (lane == 0) { sred[warp] = s; sred[8 + warp] = ss; }
    __syncthreads();
    if (t < 32) {
        s  = (t < 8) ? sred[t]     : 0.f;
        ss = (t < 8) ? sred[8 + t] : 0.f;
#pragma unroll
        for (int o = 4; o; o >>= 1) {
            s  += __shfl_xor_sync(0xffffffffu, s,  o);
            ss += __shfl_xor_sync(0xffffffffu, ss, o);
        }
        if (t == 0) { sred[0] = s; sred[1] = ss; }
    }
    __syncthreads();
    const float mean = sred[0] * (1.f / DMODEL);
    const float var  = sred[1] * (1.f / DMODEL) - mean * mean;
    const float inv  = rsqrtf(var + EPSV);
    const float4* wp = (const float4*)w;
    const float4* bp = (const float4*)b;
    float4 wv0 = wp[t], wv1 = wp[t + 256], bv0 = bp[t], bv1 = bp[t + 256];
    uint2 u0, u1;
    u0.x = packh2((v0.x - mean) * inv * wv0.x + bv0.x, (v0.y - mean) * inv * wv0.y + bv0.y);
    u0.y = packh2((v0.z - mean) * inv * wv0.z + bv0.z, (v0.w - mean) * inv * wv0.w + bv0.w);
    u1.x = packh2((v1.x - mean) * inv * wv1.x + bv1.x, (v1.y - mean) * inv * wv1.y + bv1.y);
    u1.y = packh2((v1.z - mean) * inv * wv1.z + bv1.z, (v1.w - mean) * inv * wv1.w + bv1.w);
    uint2* op = (uint2*)(out + (size_t)row * DMODEL);
    op[t] = u0;
    op[t + 256] = u1;
}

// ------- pipelined fp16 mma GEMM: C[., c_off + 0..N) = A[M,K] @ Bw[N,K]^T ---
#define ACT_NONE 0
#define ACT_GELU 1
#define GSTAGE 49152
#define GSMEM  (4 * GSTAGE)     // 192 KB

template <int ACT, bool RES, bool OUTH>
__global__ __launch_bounds__(256, 1) void gemm_h_kernel(
    const __half* __restrict__ A, const __half* __restrict__ Bw,
    const float* __restrict__ bias0, const float* __restrict__ bias1,
    const float* __restrict__ bias2, const float* __restrict__ Resid,
    void* __restrict__ Cv, int M, int N, int K, int ldC, int c_off,
    size_t aZ, size_t wZ, size_t cZ)
{
    extern __shared__ char smem[];
    const uint32_t s0 = smem_u32(smem);
    const int tid = threadIdx.x;
    const int warp = tid >> 5, lane = tid & 31;
    const int wm = (warp & 1) << 6;
    const int wn = (warp >> 1) << 6;
    const int l15 = lane & 15, lh = lane >> 4;
    const int z = blockIdx.z;
    const float* bias = (z == 0) ? bias0 : (z == 1) ? bias1 : bias2;
    const __half* Ab = A  + (size_t)z * aZ + (size_t)(blockIdx.y * 128) * K;
    const __half* Bb = Bw + (size_t)z * wZ + (size_t)(blockIdx.x * 256) * K;
    const int nk = K >> 6;

#define G_LOAD(kt)                                                            \
    {                                                                         \
        const int st_ = (kt) & 3;                                             \
        const uint32_t sA_ = s0 + st_ * GSTAGE;                               \
        const uint32_t sB_ = sA_ + 16384;                                     \
        const size_t kof_ = (size_t)(kt) * 64;                                \
        _Pragma("unroll")                                                     \
        for (int p = 0; p < 4; ++p) {                                         \
            const int cid = tid + (p << 8);                                   \
            const int row = cid >> 3, c4 = cid & 7;                           \
            const uint32_t sw = row * 128 + ((c4 ^ (row & 7)) << 4);          \
            cpasync16(sA_ + sw, Ab + (size_t)row * K + kof_ + c4 * 8);        \
        }                                                                     \
        _Pragma("unroll")                                                     \
        for (int p = 0; p < 8; ++p) {                                         \
            const int cid = tid + (p << 8);                                   \
            const int row = cid >> 3, c4 = cid & 7;                           \
            const uint32_t sw = row * 128 + ((c4 ^ (row & 7)) << 4);          \
            cpasync16(sB_ + sw, Bb + (size_t)row * K + kof_ + c4 * 8);        \
        }                                                                     \
    }

    G_LOAD(0); CP_COMMIT();
    G_LOAD(1); CP_COMMIT();
    G_LOAD(2); CP_COMMIT();

    float acc[4][8][4];
#pragma unroll
    for (int i = 0; i < 4; i++)
#pragma unroll
        for (int j = 0; j < 8; j++)
#pragma unroll
            for (int r = 0; r < 4; r++) acc[i][j][r] = 0.f;

    for (int kt = 0; kt < nk; ++kt) {
        CP_WAIT2();
        __syncthreads();
        if (kt + 3 < nk) G_LOAD(kt + 3);
        CP_COMMIT();

        const uint32_t sA = s0 + (kt & 3) * GSTAGE, sB = sA + 16384;
#pragma unroll
        for (int kk = 0; kk < 4; ++kk) {
            uint32_t af[4][4], bf[4][4];
            const int ch = (kk << 1) + lh;
#pragma unroll
            for (int i = 0; i < 4; ++i) {
                const int row = wm + i * 16 + l15;
                LDSM4(af[i], sA + row * 128 + ((ch ^ (row & 7)) << 4));
            }
#pragma unroll
            for (int jp = 0; jp < 4; ++jp) {
                const int row = wn + jp * 16 + l15;
                LDSM4(bf[jp], sB + row * 128 + ((ch ^ (row & 7)) << 4));
            }
#pragma unroll
            for (int i = 0; i < 4; ++i)
#pragma unroll
                for (int jp = 0; jp < 4; ++jp) {
                    mma_h(acc[i][2*jp],   af[i], bf[jp][0], bf[jp][2]);
                    mma_h(acc[i][2*jp+1], af[i], bf[jp][1], bf[jp][3]);
                }
        }
    }
#undef G_LOAD

    const int g = lane >> 2, tg = lane & 3;
    const int rowbase = blockIdx.y * 128 + wm;
    const int colbase = blockIdx.x * 256 + wn;
#pragma unroll
    for (int i = 0; i < 4; ++i) {
#pragma unroll
        for (int j = 0; j < 8; ++j) {
            const int r0 = rowbase + i * 16 + g;
            const int c0 = colbase + j * 8 + tg * 2;
            const float bia0 = bias[c0], bia1 = bias[c0 + 1];
#pragma unroll
            for (int hr = 0; hr < 2; ++hr) {
                const int row = r0 + hr * 8;
                float v0 = acc[i][j][hr * 2 + 0] + bia0;
                float v1 = acc[i][j][hr * 2 + 1] + bia1;
                if (RES) {
                    v0 += Resid[(size_t)row * N + c0];
                    v1 += Resid[(size_t)row * N + c0 + 1];
                }
                if (ACT == ACT_GELU) {
                    v0 = 0.5f * v0 * (1.f + erff(v0 * 0.7071067811865475f));
                    v1 = 0.5f * v1 * (1.f + erff(v1 * 0.7071067811865475f));
                }
                if (OUTH) {
                    __half* Cb = (__half*)Cv + (size_t)z * cZ;
                    *(uint32_t*)&Cb[(size_t)row * ldC + c_off + c0] = packh2(v0, v1);
                } else {
                    float* Cb = (float*)Cv + (size_t)z * cZ;
                    *(float2*)&Cb[(size_t)row * ldC + c_off + c0] = make_float2(v0, v1);
                }
            }
        }
    }
}

// ---------------- per-head rmsnorm + rope (fp16 in-place, single tensor) ----
__global__ __launch_bounds__(256) void qknorm_rope_kernel(
    __half* __restrict__ x, const float* __restrict__ w,
    const float* __restrict__ freqs)
{
    const int token = blockIdx.x;
    const int pos = token & (SEQ - 1);
    const int warp = threadIdx.x >> 5, lane = threadIdx.x & 31;
    __shared__ float rb[8][32];
    const float4 wv = ((const float4*)w)[lane];
#pragma unroll
    for (int hh = 0; hh < 2; hh++) {
        const int h = warp + hh * 8;
        __half* p = x + (size_t)token * DMODEL + h * HDIM;
        uint2 raw = ((uint2*)p)[lane];
        const __half2 h0 = *(__half2*)&raw.x, h1 = *(__half2*)&raw.y;
        float v0 = __low2float(h0), v1 = __high2float(h0);
        float v2 = __low2float(h1), v3 = __high2float(h1);
        float ssq = v0*v0 + v1*v1 + v2*v2 + v3*v3;
#pragma unroll
        for (int o = 16; o; o >>= 1) ssq += __shfl_xor_sync(0xffffffffu, ssq, o);
        const float inv = rsqrtf(ssq * (1.f / HDIM) + EPSV);
        float o0 = v0 * inv * wv.x, o1 = v1 * inv * wv.y;
        float o2 = v2 * inv * wv.z, o3 = v3 * inv * wv.w;
        const int d0 = lane * 4;
        if (d0 < 32) {
            rb[warp][d0] = o0; rb[warp][d0 + 1] = o1;
            rb[warp][d0 + 2] = o2; rb[warp][d0 + 3] = o3;
        }
        __syncwarp();
        if (d0 < 32) {
            float r[4];
#pragma unroll
            for (int i = 0; i < 4; i++) {
                const int d = d0 + i, ii = d >> 1;
                const float x1 = rb[warp][ii], x2 = rb[warp][ii + 16];
                const float c  = freqs[pos * 32 + ii * 2];
                const float sn = freqs[pos * 32 + ii * 2 + 1];
                r[i] = (d & 1) ? (x2 * c + x1 * sn) : (x1 * c - x2 * sn);
            }
            o0 = r[0]; o1 = r[1]; o2 = r[2]; o3 = r[3];
        }
        __syncwarp();
        raw.x = packh2(o0, o1);
        raw.y = packh2(o2, o3);
        ((uint2*)p)[lane] = raw;
    }
}

// ---------------- causal flash attention (fp16 mma), per-batch --------------
#define ASTAGE 16384
#define ASMEM  (4 * ASTAGE)

__global__ __launch_bounds__(128, 3) void attn_h_kernel(
    const __half* __restrict__ Q, const __half* __restrict__ Kx,
    const __half* __restrict__ Vx, __half* __restrict__ O, int b)
{
    extern __shared__ char smem[];
    const uint32_t s0 = smem_u32(smem);
    const int tid = threadIdx.x;
    const int warp = tid >> 5, lane = tid & 31;
    const int g = lane >> 2, tg = lane & 3;
    const int l15 = lane & 15, lh = lane >> 4;
    const int qb = gridDim.x - 1 - blockIdx.x;
    const int h = blockIdx.y;
    const size_t base = ((size_t)b * SEQ) * DMODEL + h * HDIM;
    const size_t obase = ((size_t)b * SEQ) * KC2 + h * HDIM;
    const int q0 = qb * 64;
    const int wq = warp * 16;
    const int nkt = (q0 >> 5) + 2;
    const int r0 = q0 + wq + g, r1 = r0 + 8;

    uint32_t aq[8][4];
    {
        const __half* q_r0 = Q + base + (size_t)r0 * DMODEL;
        const __half* q_r1 = q_r0 + (size_t)8 * DMODEL;
#pragma unroll
        for (int kk = 0; kk < 8; ++kk) {
            aq[kk][0] = *(const uint32_t*)(q_r0 + kk * 16 + tg * 2);
            aq[kk][1] = *(const uint32_t*)(q_r1 + kk * 16 + tg * 2);
            aq[kk][2] = *(const uint32_t*)(q_r0 + kk * 16 + 8 + tg * 2);
            aq[kk][3] = *(const uint32_t*)(q_r1 + kk * 16 + 8 + tg * 2);
        }
    }

#define A_LOAD(kt)                                                            \
    {                                                                         \
        const int st_ = (kt) & 3;                                             \
        const uint32_t Kst_ = s0 + st_ * ASTAGE;                              \
        const uint32_t Vst_ = Kst_ + 8192;                                    \
        const int kv0_ = (kt) << 5;                                           \
        _Pragma("unroll")                                                     \
        for (int p = 0; p < 4; ++p) {                                         \
            const int cid = tid + (p << 7);                                   \
            const int row = cid >> 4, c = cid & 15;                           \
            const uint32_t sw = row * 256 + ((c ^ (row & 7)) << 4);           \
            const size_t go = base + (size_t)(kv0_ + row) * DMODEL + c * 8;   \
            cpasync16(Kst_ + sw, Kx + go);                                    \
            cpasync16(Vst_ + sw, Vx + go);                                    \
        }                                                                     \
    }

    A_LOAD(0); CP_COMMIT();
    A_LOAD(1); CP_COMMIT();
    A_LOAD(2); CP_COMMIT();

    float m0 = -1e30f, m1 = -1e30f, l0 = 0.f, l1 = 0.f;
    float o[16][4];
#pragma unroll
    for (int nb = 0; nb < 16; ++nb)
#pragma unroll
        for (int r = 0; r < 4; ++r) o[nb][r] = 0.f;

    for (int kt = 0; kt < nkt; ++kt) {
        CP_WAIT2();
        __syncthreads();
        if (kt + 3 < nkt) A_LOAD(kt + 3);
        CP_COMMIT();

        const int kv0 = kt << 5;
        if (kv0 <= q0 + wq + 15) {
            const uint32_t Kst = s0 + (kt & 3) * ASTAGE;
            const uint32_t Vst = Kst + 8192;

            float sc[4][4];
#pragma unroll
            for (int jb = 0; jb < 4; ++jb)
#pragma unroll
                for (int r = 0; r < 4; ++r) sc[jb][r] = 0.f;
#pragma unroll
            for (int kk = 0; kk < 8; ++kk) {
                const int ch = (kk << 1) + lh;
#pragma unroll
                for (int jp = 0; jp < 2; ++jp) {
                    uint32_t bf[4];
                    const int row = jp * 16 + l15;
                    LDSM4(bf, Kst + row * 256 + ((ch ^ (row & 7)) << 4));
                    mma_h(sc[2*jp],   aq[kk], bf[0], bf[2]);
                    mma_h(sc[2*jp+1], aq[kk], bf[1], bf[3]);
                }
            }

            const bool diag = (kv0 + 31 > r0) || (kv0 + 31 > r1);
#pragma unroll
            for (int jb = 0; jb < 4; ++jb) {
                const int c0 = kv0 + jb * 8 + tg * 2;
                sc[jb][0] *= SCALE_ATT; sc[jb][1] *= SCALE_ATT;
                sc[jb][2] *= SCALE_ATT; sc[jb][3] *= SCALE_ATT;
                if (diag) {
                    if (c0     > r0) sc[jb][0] = -1e30f;
                    if (c0 + 1 > r0) sc[jb][1] = -1e30f;
                    if (c0     > r1) sc[jb][2] = -1e30f;
                    if (c0 + 1 > r1) sc[jb][3] = -1e30f;
                }
            }

            float rm0 = sc[0][0], rm1 = sc[0][2];
#pragma unroll
            for (int jb = 0; jb < 4; ++jb) {
                rm0 = fmaxf(rm0, fmaxf(sc[jb][0], sc[jb][1]));
                rm1 = fmaxf(rm1, fmaxf(sc[jb][2], sc[jb][3]));
            }
            rm0 = fmaxf(rm0, __shfl_xor_sync(0xffffffffu, rm0, 1));
            rm0 = fmaxf(rm0, __shfl_xor_sync(0xffffffffu, rm0, 2));
            rm1 = fmaxf(rm1, __shfl_xor_sync(0xffffffffu, rm1, 1));
            rm1 = fmaxf(rm1, __shfl_xor_sync(0xffffffffu, rm1, 2));
            const float mx0 = fmaxf(m0, rm0), mx1 = fmaxf(m1, rm1);
            const float corr0 = __expf(m0 - mx0), corr1 = __expf(m1 - mx1);
            float rs0 = 0.f, rs1 = 0.f;
#pragma unroll
            for (int jb = 0; jb < 4; ++jb) {
                sc[jb][0] = __expf(sc[jb][0] - mx0);
                sc[jb][1] = __expf(sc[jb][1] - mx0);
                sc[jb][2] = __expf(sc[jb][2] - mx1);
                sc[jb][3] = __expf(sc[jb][3] - mx1);
                rs0 += sc[jb][0] + sc[jb][1];
                rs1 += sc[jb][2] + sc[jb][3];
            }
            rs0 += __shfl_xor_sync(0xffffffffu, rs0, 1);
            rs0 += __shfl_xor_sync(0xffffffffu, rs0, 2);
            rs1 += __shfl_xor_sync(0xffffffffu, rs1, 1);
            rs1 += __shfl_xor_sync(0xffffffffu, rs1, 2);
            l0 = l0 * corr0 + rs0;  m0 = mx0;
            l1 = l1 * corr1 + rs1;  m1 = mx1;
#pragma unroll
            for (int nb = 0; nb < 16; ++nb) {
                o[nb][0] *= corr0; o[nb][1] *= corr0;
                o[nb][2] *= corr1; o[nb][3] *= corr1;
            }

#pragma unroll
            for (int kc = 0; kc < 2; ++kc) {
                uint32_t pa[4];
                pa[0] = packh2(sc[2*kc][0],   sc[2*kc][1]);
                pa[1] = packh2(sc[2*kc][2],   sc[2*kc][3]);
                pa[2] = packh2(sc[2*kc+1][0], sc[2*kc+1][1]);
                pa[3] = packh2(sc[2*kc+1][2], sc[2*kc+1][3]);
#pragma unroll
                for (int cp = 0; cp < 8; ++cp) {
                    uint32_t vf[4];
                    const int row = kc * 16 + l15;
                    const int ch = (cp << 1) + lh;
                    LDSM4T(vf, Vst + row * 256 + ((ch ^ (row & 7)) << 4));
                    mma_h(o[2*cp],   pa, vf[0], vf[1]);
                    mma_h(o[2*cp+1], pa, vf[2], vf[3]);
                }
            }
        }
    }
#undef A_LOAD

    const float inv0 = 1.f / l0, inv1 = 1.f / l1;
    __half* o_r0 = O + obase + (size_t)r0 * KC2;
    __half* o_r1 = O + obase + (size_t)r1 * KC2;
#pragma unroll
    for (int nb = 0; nb < 16; ++nb) {
        const int c = nb * 8 + tg * 2;
        *(uint32_t*)&o_r0[c] = packh2(o[nb][0] * inv0, o[nb][1] * inv0);
        *(uint32_t*)&o_r1[c] = packh2(o[nb][2] * inv1, o[nb][3] * inv1);
    }
}

// ---------------- launcher --------------------------------------------------
static cudaStream_t g_side = nullptr, g_side2 = nullptr;
static cudaEvent_t g_ev0 = nullptr, g_evc = nullptr, g_evln = nullptr,
                   g_evj0 = nullptr, g_evj1 = nullptr, g_evk = nullptr,
                   g_evrk = nullptr, g_evrq = nullptr, g_evF1 = nullptr;

extern "C" void kernel_launch(void* const* d_in, const int* in_sizes, int n_in,
                              void* d_out, int out_size)
{
    const float* x0      = (const float*)d_in[0];
    const float* x1      = (const float*)d_in[1];
    const float* x2      = (const float*)d_in[2];
    const float* x3      = (const float*)d_in[3];
    const float* freqs   = (const float*)d_in[5];
    const float* wq_w    = (const float*)d_in[7];
    const float* wq_b    = (const float*)d_in[8];
    const float* wk_w    = (const float*)d_in[9];
    const float* wk_b    = (const float*)d_in[10];
    const float* wv_w    = (const float*)d_in[11];
    const float* wv_b    = (const float*)d_in[12];
    const float* wo_w    = (const float*)d_in[13];
    const float* wo_b    = (const float*)d_in[14];
    const float* qn_w    = (const float*)d_in[15];
    const float* kn_w    = (const float*)d_in[16];
    const float* ln0_w   = (const float*)d_in[17];
    const float* ln0_b   = (const float*)d_in[18];
    const float* ln1_w   = (const float*)d_in[19];
    const float* ln1_b   = (const float*)d_in[20];
    const float* ln2_w   = (const float*)d_in[21];
    const float* ln2_b   = (const float*)d_in[22];
    const float* ffn_w   = (const float*)d_in[23];
    const float* ffn_b   = (const float*)d_in[24];
    const float* w1_w    = (const float*)d_in[25];
    const float* w1_b    = (const float*)d_in[26];
    const float* w2_w    = (const float*)d_in[27];
    const float* w2_b    = (const float*)d_in[28];
    float* out = (float*)d_out;

    __half* hs = nullptr;
    float* biasOW = nullptr;
    cudaGetSymbolAddress((void**)&hs, g_h);
    cudaGetSymbolAddress((void**)&biasOW, g_bias);
    __half* nq   = hs;                       // 3*CH (nq,nk,nv)
    __half* nk   = hs + CH;
    __half* fx   = hs + 3 * CH;
    __half* q    = hs + 4 * CH;
    __half* k    = hs + 5 * CH;
    __half* v    = hs + 6 * CH;
    __half* yc   = hs + 7 * CH;              // [TOK, KC2]
    __half* wq_r = yc + (size_t)TOK * KC2;
    __half* wk_r = wq_r + WQKVO_SZ;
    __half* wv_r = wk_r + WQKVO_SZ;
    __half* w1_r = wv_r + WQKVO_SZ;
    __half* wow2 = w1_r + W12_SZ;            // [DMODEL, KC2]

    if (!g_side) {
        int lo = 0, hi = 0;
        cudaDeviceGetStreamPriorityRange(&lo, &hi);
        cudaStreamCreateWithPriority(&g_side, cudaStreamNonBlocking, lo);
        cudaStreamCreateWithFlags(&g_side2, cudaStreamNonBlocking);
        cudaEventCreateWithFlags(&g_ev0,  cudaEventDisableTiming);
        cudaEventCreateWithFlags(&g_evc,  cudaEventDisableTiming);
        cudaEventCreateWithFlags(&g_evln, cudaEventDisableTiming);
        cudaEventCreateWithFlags(&g_evj0, cudaEventDisableTiming);
        cudaEventCreateWithFlags(&g_evj1, cudaEventDisableTiming);
        cudaEventCreateWithFlags(&g_evk,  cudaEventDisableTiming);
        cudaEventCreateWithFlags(&g_evrk, cudaEventDisableTiming);
        cudaEventCreateWithFlags(&g_evrq, cudaEventDisableTiming);
        cudaEventCreateWithFlags(&g_evF1, cudaEventDisableTiming);
    }

    cudaFuncSetAttribute(gemm_h_kernel<ACT_NONE, false, true>,
                         cudaFuncAttributeMaxDynamicSharedMemorySize, GSMEM);
    cudaFuncSetAttribute(gemm_h_kernel<ACT_NONE, true, false>,
                         cudaFuncAttributeMaxDynamicSharedMemorySize, GSMEM);
    cudaFuncSetAttribute(gemm_h_kernel<ACT_GELU, false, true>,
                         cudaFuncAttributeMaxDynamicSharedMemorySize, GSMEM);
    cudaFuncSetAttribute(attn_h_kernel,
                         cudaFuncAttributeMaxDynamicSharedMemorySize, ASMEM);

    const int nw4 = (int)(WQKVO_SZ / 4), nh4 = (int)(W12_SZ / 4);

    // side: weight conversion + bias sum, overlapping main-stream layernorms
    cudaEventRecord(g_ev0, 0);
    cudaStreamWaitEvent(g_side, g_ev0, 0);
    round_h6_kernel<<<dim3((nh4 + 255) / 256, 6), 256, 0, g_side>>>(
        (const float4*)wq_w, (const float4*)wk_w, (const float4*)wv_w,
        (const float4*)wo_w, (const float4*)w1_w, (const float4*)w2_w,
        (uint2*)wq_r, (uint2*)wk_r, (uint2*)wv_r, wow2, (uint2*)w1_r,
        nw4, nh4);
    bias_sum_kernel<<<(DMODEL + 255) / 256, 256, 0, g_side>>>(wo_b, w2_b, biasOW);
    cudaEventRecord(g_evc, g_side);

    // main: fused layernorms
    layernorm4_kernel<<<dim3(TOK, 4), 256>>>(
        x0, x1, x2, x3,
        ln0_w, ln1_w, ln2_w, ffn_w,
        ln0_b, ln1_b, ln2_b, ffn_b,
        nq, nq + CH, nq + 2 * CH, fx);
    cudaEventRecord(g_evln, 0);

    // side (low priority): ffn1 in two M=2048 halves -> yc cols [2048, 7936)
    cudaStreamWaitEvent(g_side, g_evln, 0);
    dim3 g1h(HID / 256, SEQ / 128, 1);
    gemm_h_kernel<ACT_GELU, false, true><<<g1h, 256, GSMEM, g_side>>>(
        fx, w1_r, w1_b, nullptr, nullptr, nullptr, yc,
        SEQ, HID, DMODEL, KC2, DMODEL, 0, 0, 0);
    cudaEventRecord(g_evj0, g_side);
    gemm_h_kernel<ACT_GELU, false, true><<<g1h, 256, GSMEM, g_side>>>(
        fx + (size_t)SEQ * DMODEL, w1_r, w1_b, nullptr, nullptr, nullptr,
        yc + (size_t)SEQ * KC2,
        SEQ, HID, DMODEL, KC2, DMODEL, 0, 0, 0);
    cudaEventRecord(g_evj1, g_side);

    // main: K projection first (needs conv + LN)
    cudaStreamWaitEvent(0, g_evc, 0);
    dim3 gk(DMODEL / 256, TOK / 128, 1);
    gemm_h_kernel<ACT_NONE, false, true><<<gk, 256, GSMEM>>>(
        nk, wk_r, wk_b, nullptr, nullptr, nullptr, k,
        TOK, DMODEL, DMODEL, DMODEL, 0, 0, 0, 0);
    cudaEventRecord(g_evk, 0);

    // side2: rope-k concurrently with Q/V projection
    cudaStreamWaitEvent(g_side2, g_evk, 0);
    qknorm_rope_kernel<<<TOK, 256, 0, g_side2>>>(k, kn_w, freqs);
    cudaEventRecord(g_evrk, g_side2);

    // main: Q + V projection (z: 0->q, 1->v via 2x strides)
    dim3 gqv(DMODEL / 256, TOK / 128, 2);
    gemm_h_kernel<ACT_NONE, false, true><<<gqv, 256, GSMEM>>>(
        nq, wq_r, wq_b, wv_b, nullptr, nullptr, q,
        TOK, DMODEL, DMODEL, DMODEL, 0, 2 * CH, 2 * WQKVO_SZ, 2 * CH);

    // main: rope-q
    qknorm_rope_kernel<<<TOK, 256>>>(q, qn_w, freqs);
    cudaEventRecord(g_evrq, 0);

    // main: attention batch 0 (needs rope-k from side2)
    cudaStreamWaitEvent(0, g_evrk, 0);
    attn_h_kernel<<<dim3(SEQ / 64, NHEAD), 128, ASMEM>>>(q, k, v, yc, 0);

    // side2: attention batch 1, concurrent with batch 0
    cudaStreamWaitEvent(g_side2, g_evrq, 0);
    attn_h_kernel<<<dim3(SEQ / 64, NHEAD), 128, ASMEM, g_side2>>>(q, k, v, yc, 1);

    // main: fused O+FFN2 half 0 (rows 0..2047) after attn b0 + ffn1 half 0
    cudaStreamWaitEvent(0, g_evj0, 0);
    dim3 gf(DMODEL / 256, SEQ / 128, 1);
    gemm_h_kernel<ACT_NONE, true, false><<<gf, 256, GSMEM>>>(
        yc, wow2, biasOW, nullptr, nullptr, x3, out,
        SEQ, DMODEL, KC2, DMODEL, 0, 0, 0, 0);

    // side2: fused O+FFN2 half 1 after attn b1 + ffn1 half 1
    cudaStreamWaitEvent(g_side2, g_evj1, 0);
    gemm_h_kernel<ACT_NONE, true, false><<<gf, 256, GSMEM, g_side2>>>(
        yc + (size_t)SEQ * KC2, wow2, biasOW, nullptr, nullptr,
        x3 + (size_t)SEQ * DMODEL, out + (size_t)SEQ * DMODEL,
        SEQ, DMODEL, KC2, DMODEL, 0, 0, 0, 0);
    cudaEventRecord(g_evF1, g_side2);

    // join side2 into main so the captured graph covers fused half 1
    cudaStreamWaitEvent(0, g_evF1, 0);
}

// round 16
// speedup vs baseline: 1.0614x; 1.0154x over previous
#include <cuda_runtime.h>
#include <cuda_fp16.h>
#include <stdint.h>

#define BATCH 2
#define SEQ   2048
#define DMODEL 2048
#define NHEAD 16
#define HDIM  128
#define HID   5888
#define TOK   (BATCH*SEQ)            // 4096
#define CH    ((size_t)TOK*DMODEL)   // 8388608
#define KC2   7936                   // DMODEL + HID (fused O+FFN2 K dim)
#define EPSV  1e-5f
#define SCALE_ATT 0.08838834764831845f

#define WQKVO_SZ ((size_t)DMODEL*DMODEL)
#define W12_SZ   ((size_t)HID*DMODEL)
#define HTOT (7*CH + (size_t)TOK*KC2 + 3*WQKVO_SZ + W12_SZ + (size_t)DMODEL*KC2)

__device__ __half g_h[HTOT];
__device__ float g_bias[DMODEL];     // wo_b + w2_b

// ---------------- helpers ---------------------------------------------------
__device__ __forceinline__ uint32_t smem_u32(const void* p) {
    uint32_t a;
    asm("{ .reg .u64 t; cvta.to.shared.u64 t, %1; cvt.u32.u64 %0, t; }"
        : "=r"(a) : "l"(p));
    return a;
}
__device__ __forceinline__ uint32_t packh2(float a, float b) {
    __half2 h = __floats2half2_rn(a, b);
    return *(uint32_t*)&h;
}
__device__ __forceinline__ void cpasync16(uint32_t dst, const void* src) {
    asm volatile("cp.async.cg.shared.global [%0], [%1], 16;" :: "r"(dst), "l"(src) : "memory");
}
#define CP_COMMIT() asm volatile("cp.async.commit_group;" ::: "memory")
#define CP_WAIT2()  asm volatile("cp.async.wait_group 2;" ::: "memory")

#define LDSM4(r, addr) \
    asm volatile("ldmatrix.sync.aligned.m8n8.x4.shared.b16 {%0,%1,%2,%3}, [%4];" \
        : "=r"((r)[0]), "=r"((r)[1]), "=r"((r)[2]), "=r"((r)[3]) : "r"(addr))
#define LDSM4T(r, addr) \
    asm volatile("ldmatrix.sync.aligned.m8n8.x4.trans.shared.b16 {%0,%1,%2,%3}, [%4];" \
        : "=r"((r)[0]), "=r"((r)[1]), "=r"((r)[2]), "=r"((r)[3]) : "r"(addr))

__device__ __forceinline__ void mma_h(float (&c)[4], const uint32_t (&a)[4],
                                      uint32_t b0, uint32_t b1) {
    asm volatile(
        "mma.sync.aligned.m16n8k16.row.col.f32.f16.f16.f32 "
        "{%0,%1,%2,%3}, {%4,%5,%6,%7}, {%8,%9}, {%0,%1,%2,%3};\n"
        : "+f"(c[0]), "+f"(c[1]), "+f"(c[2]), "+f"(c[3])
        : "r"(a[0]), "r"(a[1]), "r"(a[2]), "r"(a[3]), "r"(b0), "r"(b1));
}

// ---------------- fp32 -> fp16 weight conversion (split) --------------------
// early: wq, wk, wv (gates QKV projections)
__global__ __launch_bounds__(256) void round_qkv_kernel(
    const float4* __restrict__ s0, const float4* __restrict__ s1,
    const float4* __restrict__ s2,
    uint2* __restrict__ d0, uint2* __restrict__ d1, uint2* __restrict__ d2,
    int nw4)
{
    const int z = blockIdx.y;
    const int i = blockIdx.x * 256 + threadIdx.x;
    if (i >= nw4) return;
    const float4* in = (z == 0) ? s0 : (z == 1) ? s1 : s2;
    uint2* out = (z == 0) ? d0 : (z == 1) ? d1 : d2;
    float4 v = in[i];
    uint2 u;
    u.x = packh2(v.x, v.y);
    u.y = packh2(v.z, v.w);
    out[i] = u;
}
// late: wo(->wow2 cols 0-2047), w1, w2(->wow2 cols 2048+) — gates ffn1/fused
__global__ __launch_bounds__(256) void round_rest_kernel(
    const float4* __restrict__ s0, const float4* __restrict__ s1,
    const float4* __restrict__ s2,
    __half* __restrict__ dcw, uint2* __restrict__ d1,
    int nw4, int nh4)
{
    const int z = blockIdx.y;
    const int n4 = (z == 0) ? nw4 : nh4;
    const int i = blockIdx.x * 256 + threadIdx.x;
    if (i >= n4) return;
    const float4* in = (z == 0) ? s0 : (z == 1) ? s1 : s2;
    float4 v = in[i];
    uint2 u;
    u.x = packh2(v.x, v.y);
    u.y = packh2(v.z, v.w);
    if (z == 1) {
        d1[i] = u;
    } else if (z == 0) {
        const int e = i * 4;
        const int n = e >> 11, kk = e & 2047;
        *(uint2*)(dcw + (size_t)n * KC2 + kk) = u;
    } else {
        const int e = i * 4;
        const int n = e / HID, kk = e - n * HID;
        *(uint2*)(dcw + (size_t)n * KC2 + DMODEL + kk) = u;
    }
}

__global__ __launch_bounds__(256) void bias_sum_kernel(
    const float* __restrict__ a, const float* __restrict__ b,
    float* __restrict__ c)
{
    const int i = blockIdx.x * 256 + threadIdx.x;
    if (i < DMODEL) c[i] = a[i] + b[i];
}

// ---------------- fused layernorm x4 (fp32 in, fp16 out) --------------------
__global__ __launch_bounds__(256) void layernorm4_kernel(
    const float* __restrict__ x0, const float* __restrict__ x1,
    const float* __restrict__ x2, const float* __restrict__ x3,
    const float* __restrict__ w0, const float* __restrict__ w1,
    const float* __restrict__ w2, const float* __restrict__ w3,
    const float* __restrict__ b0p, const float* __restrict__ b1p,
    const float* __restrict__ b2p, const float* __restrict__ b3p,
    __half* __restrict__ o0p, __half* __restrict__ o1p,
    __half* __restrict__ o2p, __half* __restrict__ o3p)
{
    const int z = blockIdx.y;
    const float* x = (z == 0) ? x0 : (z == 1) ? x1 : (z == 2) ? x2 : x3;
    const float* w = (z == 0) ? w0 : (z == 1) ? w1 : (z == 2) ? w2 : w3;
    const float* b = (z == 0) ? b0p : (z == 1) ? b1p : (z == 2) ? b2p : b3p;
    __half* out    = (z == 0) ? o0p : (z == 1) ? o1p : (z == 2) ? o2p : o3p;

    const int row = blockIdx.x;
    const int t = threadIdx.x;
    const float4* xp = (const float4*)(x + (size_t)row * DMODEL);
    float4 v0 = xp[t], v1 = xp[t + 256];
    float s  = v0.x + v0.y + v0.z + v0.w + v1.x + v1.y + v1.z + v1.w;
    float ss = v0.x*v0.x + v0.y*v0.y + v0.z*v0.z + v0.w*v0.w
             + v1.x*v1.x + v1.y*v1.y + v1.z*v1.z + v1.w*v1.w;
    __shared__ float sred[16];
    const int lane = t & 31, warp = t >> 5;
#pragma unroll
    for (int o = 16; o; o >>= 1) {
        s  += __shfl_xor_sync(0xffffffffu, s,  o);
        ss += __shfl_xor_sync(0xffffffffu, ss, o);
    }
    if (lane == 0) { sred[warp] = s; sred[8 + warp] = ss; }
    __syncthreads();
    if (t < 32) {
        s  = (t < 8) ? sred[t]     : 0.f;
        ss = (t < 8) ? sred[8 + t] : 0.f;
#pragma unroll
        for (int o = 4; o; o >>= 1) {
            s  += __shfl_xor_sync(0xffffffffu, s,  o);
            ss += __shfl_xor_sync(0xffffffffu, ss, o);
        }
        if (t == 0) { sred[0] = s; sred[1] = ss; }
    }
    __syncthreads();
    const float mean = sred[0] * (1.f / DMODEL);
    const float var  = sred[1] * (1.f / DMODEL) - mean * mean;
    const float inv  = rsqrtf(var + EPSV);
    const float4* wp = (const float4*)w;
    const float4* bp = (const float4*)b;
    float4 wv0 = wp[t], wv1 = wp[t + 256], bv0 = bp[t], bv1 = bp[t + 256];
    uint2 u0, u1;
    u0.x = packh2((v0.x - mean) * inv * wv0.x + bv0.x, (v0.y - mean) * inv * wv0.y + bv0.y);
    u0.y = packh2((v0.z - mean) * inv * wv0.z + bv0.z, (v0.w - mean) * inv * wv0.w + bv0.w);
    u1.x = packh2((v1.x - mean) * inv * wv1.x + bv1.x, (v1.y - mean) * inv * wv1.y + bv1.y);
    u1.y = packh2((v1.z - mean) * inv * wv1.z + bv1.z, (v1.w - mean) * inv * wv1.w + bv1.w);
    uint2* op = (uint2*)(out + (size_t)row * DMODEL);
    op[t] = u0;
    op[t + 256] = u1;
}

// ------- pipelined fp16 mma GEMM: C[., c_off + 0..N) = A[M,K] @ Bw[N,K]^T ---
#define ACT_NONE 0
#define ACT_GELU 1
#define GSTAGE 49152
#define GSMEM  (4 * GSTAGE)     // 192 KB

template <int ACT, bool RES, bool OUTH>
__global__ __launch_bounds__(256, 1) void gemm_h_kernel(
    const __half* __restrict__ A, const __half* __restrict__ Bw,
    const float* __restrict__ bias0, const float* __restrict__ bias1,
    const float* __restrict__ bias2, const float* __restrict__ Resid,
    void* __restrict__ Cv, int M, int N, int K, int ldC, int c_off,
    size_t aZ, size_t wZ, size_t cZ)
{
    extern __shared__ char smem[];
    const uint32_t s0 = smem_u32(smem);
    const int tid = threadIdx.x;
    const int warp = tid >> 5, lane = tid & 31;
    const int wm = (warp & 1) << 6;
    const int wn = (warp >> 1) << 6;
    const int l15 = lane & 15, lh = lane >> 4;
    const int z = blockIdx.z;
    const float* bias = (z == 0) ? bias0 : (z == 1) ? bias1 : bias2;
    const __half* Ab = A  + (size_t)z * aZ + (size_t)(blockIdx.y * 128) * K;
    const __half* Bb = Bw + (size_t)z * wZ + (size_t)(blockIdx.x * 256) * K;
    const int nk = K >> 6;

#define G_LOAD(kt)                                                            \
    {                                                                         \
        const int st_ = (kt) & 3;                                             \
        const uint32_t sA_ = s0 + st_ * GSTAGE;                               \
        const uint32_t sB_ = sA_ + 16384;                                     \
        const size_t kof_ = (size_t)(kt) * 64;                                \
        _Pragma("unroll")                                                     \
        for (int p = 0; p < 4; ++p) {                                         \
            const int cid = tid + (p << 8);                                   \
            const int row = cid >> 3, c4 = cid & 7;                           \
            const uint32_t sw = row * 128 + ((c4 ^ (row & 7)) << 4);          \
            cpasync16(sA_ + sw, Ab + (size_t)row * K + kof_ + c4 * 8);        \
        }                                                                     \
        _Pragma("unroll")                                                     \
        for (int p = 0; p < 8; ++p) {                                         \
            const int cid = tid + (p << 8);                                   \
            const int row = cid >> 3, c4 = cid & 7;                           \
            const uint32_t sw = row * 128 + ((c4 ^ (row & 7)) << 4);          \
            cpasync16(sB_ + sw, Bb + (size_t)row * K + kof_ + c4 * 8);        \
        }                                                                     \
    }

    G_LOAD(0); CP_COMMIT();
    G_LOAD(1); CP_COMMIT();
    G_LOAD(2); CP_COMMIT();

    float acc[4][8][4];
#pragma unroll
    for (int i = 0; i < 4; i++)
#pragma unroll
        for (int j = 0; j < 8; j++)
#pragma unroll
            for (int r = 0; r < 4; r++) acc[i][j][r] = 0.f;

    for (int kt = 0; kt < nk; ++kt) {
        CP_WAIT2();
        __syncthreads();
        if (kt + 3 < nk) G_LOAD(kt + 3);
        CP_COMMIT();

        const uint32_t sA = s0 + (kt & 3) * GSTAGE, sB = sA + 16384;
#pragma unroll
        for (int kk = 0; kk < 4; ++kk) {
            uint32_t af[4][4], bf[4][4];
            const int ch = (kk << 1) + lh;
#pragma unroll
            for (int i = 0; i < 4; ++i) {
                const int row = wm + i * 16 + l15;
                LDSM4(af[i], sA + row * 128 + ((ch ^ (row & 7)) << 4));
            }
#pragma unroll
            for (int jp = 0; jp < 4; ++jp) {
                const int row = wn + jp * 16 + l15;
                LDSM4(bf[jp], sB + row * 128 + ((ch ^ (row & 7)) << 4));
            }
#pragma unroll
            for (int i = 0; i < 4; ++i)
#pragma unroll
                for (int jp = 0; jp < 4; ++jp) {
                    mma_h(acc[i][2*jp],   af[i], bf[jp][0], bf[jp][2]);
                    mma_h(acc[i][2*jp+1], af[i], bf[jp][1], bf[jp][3]);
                }
        }
    }
#undef G_LOAD

    const int g = lane >> 2, tg = lane & 3;
    const int rowbase = blockIdx.y * 128 + wm;
    const int colbase = blockIdx.x * 256 + wn;
#pragma unroll
    for (int i = 0; i < 4; ++i) {
#pragma unroll
        for (int j = 0; j < 8; ++j) {
            const int r0 = rowbase + i * 16 + g;
            const int c0 = colbase + j * 8 + tg * 2;
            const float bia0 = bias[c0], bia1 = bias[c0 + 1];
#pragma unroll
            for (int hr = 0; hr < 2; ++hr) {
                const int row = r0 + hr * 8;
                float v0 = acc[i][j][hr * 2 + 0] + bia0;
                float v1 = acc[i][j][hr * 2 + 1] + bia1;
                if (RES) {
                    v0 += Resid[(size_t)row * N + c0];
                    v1 += Resid[(size_t)row * N + c0 + 1];
                }
                if (ACT == ACT_GELU) {
                    v0 = 0.5f * v0 * (1.f + erff(v0 * 0.7071067811865475f));
                    v1 = 0.5f * v1 * (1.f + erff(v1 * 0.7071067811865475f));
                }
                if (OUTH) {
                    __half* Cb = (__half*)Cv + (size_t)z * cZ;
                    *(uint32_t*)&Cb[(size_t)row * ldC + c_off + c0] = packh2(v0, v1);
                } else {
                    float* Cb = (float*)Cv + (size_t)z * cZ;
                    *(float2*)&Cb[(size_t)row * ldC + c_off + c0] = make_float2(v0, v1);
                }
            }
        }
    }
}

// ---------------- per-head rmsnorm + rope (fp16 in-place, single tensor) ----
__global__ __launch_bounds__(256) void qknorm_rope_kernel(
    __half* __restrict__ x, const float* __restrict__ w,
    const float* __restrict__ freqs)
{
    const int token = blockIdx.x;
    const int pos = token & (SEQ - 1);
    const int warp = threadIdx.x >> 5, lane = threadIdx.x & 31;
    __shared__ float rb[8][32];
    const float4 wv = ((const float4*)w)[lane];
#pragma unroll
    for (int hh = 0; hh < 2; hh++) {
        const int h = warp + hh * 8;
        __half* p = x + (size_t)token * DMODEL + h * HDIM;
        uint2 raw = ((uint2*)p)[lane];
        const __half2 h0 = *(__half2*)&raw.x, h1 = *(__half2*)&raw.y;
        float v0 = __low2float(h0), v1 = __high2float(h0);
        float v2 = __low2float(h1), v3 = __high2float(h1);
        float ssq = v0*v0 + v1*v1 + v2*v2 + v3*v3;
#pragma unroll
        for (int o = 16; o; o >>= 1) ssq += __shfl_xor_sync(0xffffffffu, ssq, o);
        const float inv = rsqrtf(ssq * (1.f / HDIM) + EPSV);
        float o0 = v0 * inv * wv.x, o1 = v1 * inv * wv.y;
        float o2 = v2 * inv * wv.z, o3 = v3 * inv * wv.w;
        const int d0 = lane * 4;
        if (d0 < 32) {
            rb[warp][d0] = o0; rb[warp][d0 + 1] = o1;
            rb[warp][d0 + 2] = o2; rb[warp][d0 + 3] = o3;
        }
        __syncwarp();
        if (d0 < 32) {
            float r[4];
#pragma unroll
            for (int i = 0; i < 4; i++) {
                const int d = d0 + i, ii = d >> 1;
                const float x1 = rb[warp][ii], x2 = rb[warp][ii + 16];
                const float c  = freqs[pos * 32 + ii * 2];
                const float sn = freqs[pos * 32 + ii * 2 + 1];
                r[i] = (d & 1) ? (x2 * c + x1 * sn) : (x1 * c - x2 * sn);
            }
            o0 = r[0]; o1 = r[1]; o2 = r[2]; o3 = r[3];
        }
        __syncwarp();
        raw.x = packh2(o0, o1);
        raw.y = packh2(o2, o3);
        ((uint2*)p)[lane] = raw;
    }
}

// ---------------- causal flash attention (fp16 mma), per-batch --------------
#define ASTAGE 16384
#define ASMEM  (4 * ASTAGE)

__global__ __launch_bounds__(128, 3) void attn_h_kernel(
    const __half* __restrict__ Q, const __half* __restrict__ Kx,
    const __half* __restrict__ Vx, __half* __restrict__ O, int b)
{
    extern __shared__ char smem[];
    const uint32_t s0 = smem_u32(smem);
    const int tid = threadIdx.x;
    const int warp = tid >> 5, lane = tid & 31;
    const int g = lane >> 2, tg = lane & 3;
    const int l15 = lane & 15, lh = lane >> 4;
    const int qb = gridDim.x - 1 - blockIdx.x;
    const int h = blockIdx.y;
    const size_t base = ((size_t)b * SEQ) * DMODEL + h * HDIM;
    const size_t obase = ((size_t)b * SEQ) * KC2 + h * HDIM;
    const int q0 = qb * 64;
    const int wq = warp * 16;
    const int nkt = (q0 >> 5) + 2;
    const int r0 = q0 + wq + g, r1 = r0 + 8;

    uint32_t aq[8][4];
    {
        const __half* q_r0 = Q + base + (size_t)r0 * DMODEL;
        const __half* q_r1 = q_r0 + (size_t)8 * DMODEL;
#pragma unroll
        for (int kk = 0; kk < 8; ++kk) {
            aq[kk][0] = *(const uint32_t*)(q_r0 + kk * 16 + tg * 2);
            aq[kk][1] = *(const uint32_t*)(q_r1 + kk * 16 + tg * 2);
            aq[kk][2] = *(const uint32_t*)(q_r0 + kk * 16 + 8 + tg * 2);
            aq[kk][3] = *(const uint32_t*)(q_r1 + kk * 16 + 8 + tg * 2);
        }
    }

#define A_LOAD(kt)                                                            \
    {                                                                         \
        const int st_ = (kt) & 3;                                             \
        const uint32_t Kst_ = s0 + st_ * ASTAGE;                              \
        const uint32_t Vst_ = Kst_ + 8192;                                    \
        const int kv0_ = (kt) << 5;                                           \
        _Pragma("unroll")                                                     \
        for (int p = 0; p < 4; ++p) {                                         \
            const int cid = tid + (p << 7);                                   \
            const int row = cid >> 4, c = cid & 15;                           \
            const uint32_t sw = row * 256 + ((c ^ (row & 7)) << 4);           \
            const size_t go = base + (size_t)(kv0_ + row) * DMODEL + c * 8;   \
            cpasync16(Kst_ + sw, Kx + go);                                    \
            cpasync16(Vst_ + sw, Vx + go);                                    \
        }                                                                     \
    }

    A_LOAD(0); CP_COMMIT();
    A_LOAD(1); CP_COMMIT();
    A_LOAD(2); CP_COMMIT();

    float m0 = -1e30f, m1 = -1e30f, l0 = 0.f, l1 = 0.f;
    float o[16][4];
#pragma unroll
    for (int nb = 0; nb < 16; ++nb)
#pragma unroll
        for (int r = 0; r < 4; ++r) o[nb][r] = 0.f;

    for (int kt = 0; kt < nkt; ++kt) {
        CP_WAIT2();
        __syncthreads();
        if (kt + 3 < nkt) A_LOAD(kt + 3);
        CP_COMMIT();

        const int kv0 = kt << 5;
        if (kv0 <= q0 + wq + 15) {
            const uint32_t Kst = s0 + (kt & 3) * ASTAGE;
            const uint32_t Vst = Kst + 8192;

            float sc[4][4];
#pragma unroll
            for (int jb = 0; jb < 4; ++jb)
#pragma unroll
                for (int r = 0; r < 4; ++r) sc[jb][r] = 0.f;
#pragma unroll
            for (int kk = 0; kk < 8; ++kk) {
                const int ch = (kk << 1) + lh;
#pragma unroll
                for (int jp = 0; jp < 2; ++jp) {
                    uint32_t bf[4];
                    const int row = jp * 16 + l15;
                    LDSM4(bf, Kst + row * 256 + ((ch ^ (row & 7)) << 4));
                    mma_h(sc[2*jp],   aq[kk], bf[0], bf[2]);
                    mma_h(sc[2*jp+1], aq[kk], bf[1], bf[3]);
                }
            }

            const bool diag = (kv0 + 31 > r0) || (kv0 + 31 > r1);
#pragma unroll
            for (int jb = 0; jb < 4; ++jb) {
                const int c0 = kv0 + jb * 8 + tg * 2;
                sc[jb][0] *= SCALE_ATT; sc[jb][1] *= SCALE_ATT;
                sc[jb][2] *= SCALE_ATT; sc[jb][3] *= SCALE_ATT;
                if (diag) {
                    if (c0     > r0) sc[jb][0] = -1e30f;
                    if (c0 + 1 > r0) sc[jb][1] = -1e30f;
                    if (c0     > r1) sc[jb][2] = -1e30f;
                    if (c0 + 1 > r1) sc[jb][3] = -1e30f;
                }
            }

            float rm0 = sc[0][0], rm1 = sc[0][2];
#pragma unroll
            for (int jb = 0; jb < 4; ++jb) {
                rm0 = fmaxf(rm0, fmaxf(sc[jb][0], sc[jb][1]));
                rm1 = fmaxf(rm1, fmaxf(sc[jb][2], sc[jb][3]));
            }
            rm0 = fmaxf(rm0, __shfl_xor_sync(0xffffffffu, rm0, 1));
            rm0 = fmaxf(rm0, __shfl_xor_sync(0xffffffffu, rm0, 2));
            rm1 = fmaxf(rm1, __shfl_xor_sync(0xffffffffu, rm1, 1));
            rm1 = fmaxf(rm1, __shfl_xor_sync(0xffffffffu, rm1, 2));
            const float mx0 = fmaxf(m0, rm0), mx1 = fmaxf(m1, rm1);
            const float corr0 = __expf(m0 - mx0), corr1 = __expf(m1 - mx1);
            float rs0 = 0.f, rs1 = 0.f;
#pragma unroll
            for (int jb = 0; jb < 4; ++jb) {
                sc[jb][0] = __expf(sc[jb][0] - mx0);
                sc[jb][1] = __expf(sc[jb][1] - mx0);
                sc[jb][2] = __expf(sc[jb][2] - mx1);
                sc[jb][3] = __expf(sc[jb][3] - mx1);
                rs0 += sc[jb][0] + sc[jb][1];
                rs1 += sc[jb][2] + sc[jb][3];
            }
            rs0 += __shfl_xor_sync(0xffffffffu, rs0, 1);
            rs0 += __shfl_xor_sync(0xffffffffu, rs0, 2);
            rs1 += __shfl_xor_sync(0xffffffffu, rs1, 1);
            rs1 += __shfl_xor_sync(0xffffffffu, rs1, 2);
            l0 = l0 * corr0 + rs0;  m0 = mx0;
            l1 = l1 * corr1 + rs1;  m1 = mx1;
#pragma unroll
            for (int nb = 0; nb < 16; ++nb) {
                o[nb][0] *= corr0; o[nb][1] *= corr0;
                o[nb][2] *= corr1; o[nb][3] *= corr1;
            }

#pragma unroll
            for (int kc = 0; kc < 2; ++kc) {
                uint32_t pa[4];
                pa[0] = packh2(sc[2*kc][0],   sc[2*kc][1]);
                pa[1] = packh2(sc[2*kc][2],   sc[2*kc][3]);
                pa[2] = packh2(sc[2*kc+1][0], sc[2*kc+1][1]);
                pa[3] = packh2(sc[2*kc+1][2], sc[2*kc+1][3]);
#pragma unroll
                for (int cp = 0; cp < 8; ++cp) {
                    uint32_t vf[4];
                    const int row = kc * 16 + l15;
                    const int ch = (cp << 1) + lh;
                    LDSM4T(vf, Vst + row * 256 + ((ch ^ (row & 7)) << 4));
                    mma_h(o[2*cp],   pa, vf[0], vf[1]);
                    mma_h(o[2*cp+1], pa, vf[2], vf[3]);
                }
            }
        }
    }
#undef A_LOAD

    const float inv0 = 1.f / l0, inv1 = 1.f / l1;
    __half* o_r0 = O + obase + (size_t)r0 * KC2;
    __half* o_r1 = O + obase + (size_t)r1 * KC2;
#pragma unroll
    for (int nb = 0; nb < 16; ++nb) {
        const int c = nb * 8 + tg * 2;
        *(uint32_t*)&o_r0[c] = packh2(o[nb][0] * inv0, o[nb][1] * inv0);
        *(uint32_t*)&o_r1[c] = packh2(o[nb][2] * inv1, o[nb][3] * inv1);
    }
}

// ---------------- launcher --------------------------------------------------
static cudaStream_t g_side = nullptr, g_side2 = nullptr;
static cudaEvent_t g_ev0 = nullptr, g_evc = nullptr, g_evln = nullptr,
                   g_evj0 = nullptr, g_evj1 = nullptr, g_evk = nullptr,
                   g_evrk = nullptr, g_evrq = nullptr, g_evF1 = nullptr;

extern "C" void kernel_launch(void* const* d_in, const int* in_sizes, int n_in,
                              void* d_out, int out_size)
{
    const float* x0      = (const float*)d_in[0];
    const float* x1      = (const float*)d_in[1];
    const float* x2      = (const float*)d_in[2];
    const float* x3      = (const float*)d_in[3];
    const float* freqs   = (const float*)d_in[5];
    const float* wq_w    = (const float*)d_in[7];
    const float* wq_b    = (const float*)d_in[8];
    const float* wk_w    = (const float*)d_in[9];
    const float* wk_b    = (const float*)d_in[10];
    const float* wv_w    = (const float*)d_in[11];
    const float* wv_b    = (const float*)d_in[12];
    const float* wo_w    = (const float*)d_in[13];
    const float* wo_b    = (const float*)d_in[14];
    const float* qn_w    = (const float*)d_in[15];
    const float* kn_w    = (const float*)d_in[16];
    const float* ln0_w   = (const float*)d_in[17];
    const float* ln0_b   = (const float*)d_in[18];
    const float* ln1_w   = (const float*)d_in[19];
    const float* ln1_b   = (const float*)d_in[20];
    const float* ln2_w   = (const float*)d_in[21];
    const float* ln2_b   = (const float*)d_in[22];
    const float* ffn_w   = (const float*)d_in[23];
    const float* ffn_b   = (const float*)d_in[24];
    const float* w1_w    = (const float*)d_in[25];
    const float* w1_b    = (const float*)d_in[26];
    const float* w2_w    = (const float*)d_in[27];
    const float* w2_b    = (const float*)d_in[28];
    float* out = (float*)d_out;

    __half* hs = nullptr;
    float* biasOW = nullptr;
    cudaGetSymbolAddress((void**)&hs, g_h);
    cudaGetSymbolAddress((void**)&biasOW, g_bias);
    __half* nq   = hs;                       // 3*CH (nq,nk,nv)
    __half* nk   = hs + CH;
    __half* fx   = hs + 3 * CH;
    __half* q    = hs + 4 * CH;
    __half* k    = hs + 5 * CH;
    __half* v    = hs + 6 * CH;
    __half* yc   = hs + 7 * CH;              // [TOK, KC2]
    __half* wq_r = yc + (size_t)TOK * KC2;
    __half* wk_r = wq_r + WQKVO_SZ;
    __half* wv_r = wk_r + WQKVO_SZ;
    __half* w1_r = wv_r + WQKVO_SZ;
    __half* wow2 = w1_r + W12_SZ;            // [DMODEL, KC2]

    if (!g_side) {
        int lo = 0, hi = 0;
        cudaDeviceGetStreamPriorityRange(&lo, &hi);
        cudaStreamCreateWithPriority(&g_side, cudaStreamNonBlocking, lo);
        cudaStreamCreateWithFlags(&g_side2, cudaStreamNonBlocking);
        cudaEventCreateWithFlags(&g_ev0,  cudaEventDisableTiming);
        cudaEventCreateWithFlags(&g_evc,  cudaEventDisableTiming);
        cudaEventCreateWithFlags(&g_evln, cudaEventDisableTiming);
        cudaEventCreateWithFlags(&g_evj0, cudaEventDisableTiming);
        cudaEventCreateWithFlags(&g_evj1, cudaEventDisableTiming);
        cudaEventCreateWithFlags(&g_evk,  cudaEventDisableTiming);
        cudaEventCreateWithFlags(&g_evrk, cudaEventDisableTiming);
        cudaEventCreateWithFlags(&g_evrq, cudaEventDisableTiming);
        cudaEventCreateWithFlags(&g_evF1, cudaEventDisableTiming);
    }

    cudaFuncSetAttribute(gemm_h_kernel<ACT_NONE, false, true>,
                         cudaFuncAttributeMaxDynamicSharedMemorySize, GSMEM);
    cudaFuncSetAttribute(gemm_h_kernel<ACT_NONE, true, false>,
                         cudaFuncAttributeMaxDynamicSharedMemorySize, GSMEM);
    cudaFuncSetAttribute(gemm_h_kernel<ACT_GELU, false, true>,
                         cudaFuncAttributeMaxDynamicSharedMemorySize, GSMEM);
    cudaFuncSetAttribute(attn_h_kernel,
                         cudaFuncAttributeMaxDynamicSharedMemorySize, ASMEM);

    const int nw4 = (int)(WQKVO_SZ / 4), nh4 = (int)(W12_SZ / 4);

    // side: convert wq/wk/wv first (gates QKV), then wo/w1/w2 + bias sum
    cudaEventRecord(g_ev0, 0);
    cudaStreamWaitEvent(g_side, g_ev0, 0);
    round_qkv_kernel<<<dim3((nw4 + 255) / 256, 3), 256, 0, g_side>>>(
        (const float4*)wq_w, (const float4*)wk_w, (const float4*)wv_w,
        (uint2*)wq_r, (uint2*)wk_r, (uint2*)wv_r, nw4);
    cudaEventRecord(g_evc, g_side);
    round_rest_kernel<<<dim3((nh4 + 255) / 256, 3), 256, 0, g_side>>>(
        (const float4*)wo_w, (const float4*)w1_w, (const float4*)w2_w,
        wow2, (uint2*)w1_r, nw4, nh4);
    bias_sum_kernel<<<(DMODEL + 255) / 256, 256, 0, g_side>>>(wo_b, w2_b, biasOW);

    // main: fused layernorms
    layernorm4_kernel<<<dim3(TOK, 4), 256>>>(
        x0, x1, x2, x3,
        ln0_w, ln1_w, ln2_w, ffn_w,
        ln0_b, ln1_b, ln2_b, ffn_b,
        nq, nq + CH, nq + 2 * CH, fx);
    cudaEventRecord(g_evln, 0);

    // side (low priority): ffn1 in two M=2048 halves -> yc cols [2048, 7936)
    // (in-order after round_rest, so w1_r is ready)
    cudaStreamWaitEvent(g_side, g_evln, 0);
    dim3 g1h(HID / 256, SEQ / 128, 1);
    gemm_h_kernel<ACT_GELU, false, true><<<g1h, 256, GSMEM, g_side>>>(
        fx, w1_r, w1_b, nullptr, nullptr, nullptr, yc,
        SEQ, HID, DMODEL, KC2, DMODEL, 0, 0, 0);
    cudaEventRecord(g_evj0, g_side);
    gemm_h_kernel<ACT_GELU, false, true><<<g1h, 256, GSMEM, g_side>>>(
        fx + (size_t)SEQ * DMODEL, w1_r, w1_b, nullptr, nullptr, nullptr,
        yc + (size_t)SEQ * KC2,
        SEQ, HID, DMODEL, KC2, DMODEL, 0, 0, 0);
    cudaEventRecord(g_evj1, g_side);

    // main: K projection first (needs qkv conv + LN)
    cudaStreamWaitEvent(0, g_evc, 0);
    dim3 gk(DMODEL / 256, TOK / 128, 1);
    gemm_h_kernel<ACT_NONE, false, true><<<gk, 256, GSMEM>>>(
        nk, wk_r, wk_b, nullptr, nullptr, nullptr, k,
        TOK, DMODEL, DMODEL, DMODEL, 0, 0, 0, 0);
    cudaEventRecord(g_evk, 0);

    // side2: rope-k concurrently with Q/V projection
    cudaStreamWaitEvent(g_side2, g_evk, 0);
    qknorm_rope_kernel<<<TOK, 256, 0, g_side2>>>(k, kn_w, freqs);
    cudaEventRecord(g_evrk, g_side2);

    // main: Q + V projection (z: 0->q, 1->v via 2x strides)
    dim3 gqv(DMODEL / 256, TOK / 128, 2);
    gemm_h_kernel<ACT_NONE, false, true><<<gqv, 256, GSMEM>>>(
        nq, wq_r, wq_b, wv_b, nullptr, nullptr, q,
        TOK, DMODEL, DMODEL, DMODEL, 0, 2 * CH, 2 * WQKVO_SZ, 2 * CH);

    // main: rope-q
    qknorm_rope_kernel<<<TOK, 256>>>(q, qn_w, freqs);
    cudaEventRecord(g_evrq, 0);

    // main: attention batch 0 (needs rope-k from side2)
    cudaStreamWaitEvent(0, g_evrk, 0);
    attn_h_kernel<<<dim3(SEQ / 64, NHEAD), 128, ASMEM>>>(q, k, v, yc, 0);

    // side2: attention batch 1, concurrent with batch 0
    cudaStreamWaitEvent(g_side2, g_evrq, 0);
    attn_h_kernel<<<dim3(SEQ / 64, NHEAD), 128, ASMEM, g_side2>>>(q, k, v, yc, 1);

    // main: fused O+FFN2 half 0 (rows 0..2047) after attn b0 + ffn1 half 0
    cudaStreamWaitEvent(0, g_evj0, 0);
    dim3 gf(DMODEL / 256, SEQ / 128, 1);
    gemm_h_kernel<ACT_NONE, true, false><<<gf, 256, GSMEM>>>(
        yc, wow2, biasOW, nullptr, nullptr, x3, out,
        SEQ, DMODEL, KC2, DMODEL, 0, 0, 0, 0);

    // side2: fused O+FFN2 half 1 after attn b1 + ffn1 half 1
    cudaStreamWaitEvent(g_side2, g_evj1, 0);
    gemm_h_kernel<ACT_NONE, true, false><<<gf, 256, GSMEM, g_side2>>>(
        yc + (size_t)SEQ * KC2, wow2, biasOW, nullptr, nullptr,
        x3 + (size_t)SEQ * DMODEL, out + (size_t)SEQ * DMODEL,
        SEQ, DMODEL, KC2, DMODEL, 0, 0, 0, 0);
    cudaEventRecord(g_evF1, g_side2);

    // join side2 into main so the captured graph covers fused half 1
    cudaStreamWaitEvent(0, g_evF1, 0);
}

// round 17
// speedup vs baseline: 1.0688x; 1.0070x over previous
#include <cuda_runtime.h>
#include <cuda_fp16.h>
#include <stdint.h>

#define BATCH 2
#define SEQ   2048
#define DMODEL 2048
#define NHEAD 16
#define HDIM  128
#define HID   5888
#define TOK   (BATCH*SEQ)            // 4096
#define CH    ((size_t)TOK*DMODEL)   // 8388608
#define KC2   7936                   // DMODEL + HID (fused O+FFN2 K dim)
#define EPSV  1e-5f
#define SCALE_ATT 0.08838834764831845f

#define WQKVO_SZ ((size_t)DMODEL*DMODEL)
#define W12_SZ   ((size_t)HID*DMODEL)
#define HTOT (7*CH + (size_t)TOK*KC2 + 3*WQKVO_SZ + W12_SZ + (size_t)DMODEL*KC2)

__device__ __half g_h[HTOT];
__device__ float g_bias[DMODEL];     // wo_b + w2_b

// ---------------- helpers ---------------------------------------------------
__device__ __forceinline__ uint32_t smem_u32(const void* p) {
    uint32_t a;
    asm("{ .reg .u64 t; cvta.to.shared.u64 t, %1; cvt.u32.u64 %0, t; }"
        : "=r"(a) : "l"(p));
    return a;
}
__device__ __forceinline__ uint32_t packh2(float a, float b) {
    __half2 h = __floats2half2_rn(a, b);
    return *(uint32_t*)&h;
}
__device__ __forceinline__ void cpasync16(uint32_t dst, const void* src) {
    asm volatile("cp.async.cg.shared.global [%0], [%1], 16;" :: "r"(dst), "l"(src) : "memory");
}
#define CP_COMMIT() asm volatile("cp.async.commit_group;" ::: "memory")
#define CP_WAIT2()  asm volatile("cp.async.wait_group 2;" ::: "memory")

#define LDSM4(r, addr) \
    asm volatile("ldmatrix.sync.aligned.m8n8.x4.shared.b16 {%0,%1,%2,%3}, [%4];" \
        : "=r"((r)[0]), "=r"((r)[1]), "=r"((r)[2]), "=r"((r)[3]) : "r"(addr))
#define LDSM4T(r, addr) \
    asm volatile("ldmatrix.sync.aligned.m8n8.x4.trans.shared.b16 {%0,%1,%2,%3}, [%4];" \
        : "=r"((r)[0]), "=r"((r)[1]), "=r"((r)[2]), "=r"((r)[3]) : "r"(addr))

__device__ __forceinline__ void mma_h(float (&c)[4], const uint32_t (&a)[4],
                                      uint32_t b0, uint32_t b1) {
    asm volatile(
        "mma.sync.aligned.m16n8k16.row.col.f32.f16.f16.f32 "
        "{%0,%1,%2,%3}, {%4,%5,%6,%7}, {%8,%9}, {%0,%1,%2,%3};\n"
        : "+f"(c[0]), "+f"(c[1]), "+f"(c[2]), "+f"(c[3])
        : "r"(a[0]), "r"(a[1]), "r"(a[2]), "r"(a[3]), "r"(b0), "r"(b1));
}

// ---------------- fp32 -> fp16 weight conversion (split finer) --------------
__global__ __launch_bounds__(256) void round_one_kernel(
    const float4* __restrict__ s0, uint2* __restrict__ d0, int n4)
{
    const int i = blockIdx.x * 256 + threadIdx.x;
    if (i >= n4) return;
    float4 v = s0[i];
    uint2 u;
    u.x = packh2(v.x, v.y);
    u.y = packh2(v.z, v.w);
    d0[i] = u;
}
__global__ __launch_bounds__(256) void round_qv_kernel(
    const float4* __restrict__ s0, const float4* __restrict__ s1,
    uint2* __restrict__ d0, uint2* __restrict__ d1, int nw4)
{
    const int z = blockIdx.y;
    const int i = blockIdx.x * 256 + threadIdx.x;
    if (i >= nw4) return;
    const float4* in = (z == 0) ? s0 : s1;
    uint2* out = (z == 0) ? d0 : d1;
    float4 v = in[i];
    uint2 u;
    u.x = packh2(v.x, v.y);
    u.y = packh2(v.z, v.w);
    out[i] = u;
}
// wo(->wow2 cols 0-2047), w1, w2(->wow2 cols 2048+)
__global__ __launch_bounds__(256) void round_rest_kernel(
    const float4* __restrict__ s0, const float4* __restrict__ s1,
    const float4* __restrict__ s2,
    __half* __restrict__ dcw, uint2* __restrict__ d1,
    int nw4, int nh4)
{
    const int z = blockIdx.y;
    const int n4 = (z == 0) ? nw4 : nh4;
    const int i = blockIdx.x * 256 + threadIdx.x;
    if (i >= n4) return;
    const float4* in = (z == 0) ? s0 : (z == 1) ? s1 : s2;
    float4 v = in[i];
    uint2 u;
    u.x = packh2(v.x, v.y);
    u.y = packh2(v.z, v.w);
    if (z == 1) {
        d1[i] = u;
    } else if (z == 0) {
        const int e = i * 4;
        const int n = e >> 11, kk = e & 2047;
        *(uint2*)(dcw + (size_t)n * KC2 + kk) = u;
    } else {
        const int e = i * 4;
        const int n = e / HID, kk = e - n * HID;
        *(uint2*)(dcw + (size_t)n * KC2 + DMODEL + kk) = u;
    }
}

__global__ __launch_bounds__(256) void bias_sum_kernel(
    const float* __restrict__ a, const float* __restrict__ b,
    float* __restrict__ c)
{
    const int i = blockIdx.x * 256 + threadIdx.x;
    if (i < DMODEL) c[i] = a[i] + b[i];
}

// ---------------- layernorm (fp32 in, fp16 out); z selects up to 3 ----------
__device__ __forceinline__ void ln_body(
    const float* __restrict__ x, const float* __restrict__ w,
    const float* __restrict__ b, __half* __restrict__ out, int row)
{
    const int t = threadIdx.x;
    const float4* xp = (const float4*)(x + (size_t)row * DMODEL);
    float4 v0 = xp[t], v1 = xp[t + 256];
    float s  = v0.x + v0.y + v0.z + v0.w + v1.x + v1.y + v1.z + v1.w;
    float ss = v0.x*v0.x + v0.y*v0.y + v0.z*v0.z + v0.w*v0.w
             + v1.x*v1.x + v1.y*v1.y + v1.z*v1.z + v1.w*v1.w;
    __shared__ float sred[16];
    const int lane = t & 31, warp = t >> 5;
#pragma unroll
    for (int o = 16; o; o >>= 1) {
        s  += __shfl_xor_sync(0xffffffffu, s,  o);
        ss += __shfl_xor_sync(0xffffffffu, ss, o);
    }
    if (lane == 0) { sred[warp] = s; sred[8 + warp] = ss; }
    __syncthreads();
    if (t < 32) {
        s  = (t < 8) ? sred[t]     : 0.f;
        ss = (t < 8) ? sred[8 + t] : 0.f;
#pragma unroll
        for (int o = 4; o; o >>= 1) {
            s  += __shfl_xor_sync(0xffffffffu, s,  o);
            ss += __shfl_xor_sync(0xffffffffu, ss, o);
        }
        if (t == 0) { sred[0] = s; sred[1] = ss; }
    }
    __syncthreads();
    const float mean = sred[0] * (1.f / DMODEL);
    const float var  = sred[1] * (1.f / DMODEL) - mean * mean;
    const float inv  = rsqrtf(var + EPSV);
    const float4* wp = (const float4*)w;
    const float4* bp = (const float4*)b;
    float4 wv0 = wp[t], wv1 = wp[t + 256], bv0 = bp[t], bv1 = bp[t + 256];
    uint2 u0, u1;
    u0.x = packh2((v0.x - mean) * inv * wv0.x + bv0.x, (v0.y - mean) * inv * wv0.y + bv0.y);
    u0.y = packh2((v0.z - mean) * inv * wv0.z + bv0.z, (v0.w - mean) * inv * wv0.w + bv0.w);
    u1.x = packh2((v1.x - mean) * inv * wv1.x + bv1.x, (v1.y - mean) * inv * wv1.y + bv1.y);
    u1.y = packh2((v1.z - mean) * inv * wv1.z + bv1.z, (v1.w - mean) * inv * wv1.w + bv1.w);
    uint2* op = (uint2*)(out + (size_t)row * DMODEL);
    op[t] = u0;
    op[t + 256] = u1;
}

__global__ __launch_bounds__(256) void layernorm1_kernel(
    const float* __restrict__ x, const float* __restrict__ w,
    const float* __restrict__ b, __half* __restrict__ out)
{
    ln_body(x, w, b, out, blockIdx.x);
}

__global__ __launch_bounds__(256) void layernorm3_kernel(
    const float* __restrict__ x0, const float* __restrict__ x1,
    const float* __restrict__ x2,
    const float* __restrict__ w0, const float* __restrict__ w1,
    const float* __restrict__ w2,
    const float* __restrict__ b0p, const float* __restrict__ b1p,
    const float* __restrict__ b2p,
    __half* __restrict__ o0p, __half* __restrict__ o1p,
    __half* __restrict__ o2p)
{
    const int z = blockIdx.y;
    const float* x = (z == 0) ? x0 : (z == 1) ? x1 : x2;
    const float* w = (z == 0) ? w0 : (z == 1) ? w1 : w2;
    const float* b = (z == 0) ? b0p : (z == 1) ? b1p : b2p;
    __half* out    = (z == 0) ? o0p : (z == 1) ? o1p : o2p;
    ln_body(x, w, b, out, blockIdx.x);
}

// ------- pipelined fp16 mma GEMM: C[., c_off + 0..N) = A[M,K] @ Bw[N,K]^T ---
#define ACT_NONE 0
#define ACT_GELU 1
#define GSTAGE 49152
#define GSMEM  (4 * GSTAGE)     // 192 KB

template <int ACT, bool RES, bool OUTH>
__global__ __launch_bounds__(256, 1) void gemm_h_kernel(
    const __half* __restrict__ A, const __half* __restrict__ Bw,
    const float* __restrict__ bias0, const float* __restrict__ bias1,
    const float* __restrict__ bias2, const float* __restrict__ Resid,
    void* __restrict__ Cv, int M, int N, int K, int ldC, int c_off,
    size_t aZ, size_t wZ, size_t cZ)
{
    extern __shared__ char smem[];
    const uint32_t s0 = smem_u32(smem);
    const int tid = threadIdx.x;
    const int warp = tid >> 5, lane = tid & 31;
    const int wm = (warp & 1) << 6;
    const int wn = (warp >> 1) << 6;
    const int l15 = lane & 15, lh = lane >> 4;
    const int z = blockIdx.z;
    const float* bias = (z == 0) ? bias0 : (z == 1) ? bias1 : bias2;
    const __half* Ab = A  + (size_t)z * aZ + (size_t)(blockIdx.y * 128) * K;
    const __half* Bb = Bw + (size_t)z * wZ + (size_t)(blockIdx.x * 256) * K;
    const int nk = K >> 6;

#define G_LOAD(kt)                                                            \
    {                                                                         \
        const int st_ = (kt) & 3;                                             \
        const uint32_t sA_ = s0 + st_ * GSTAGE;                               \
        const uint32_t sB_ = sA_ + 16384;                                     \
        const size_t kof_ = (size_t)(kt) * 64;                                \
        _Pragma("unroll")                                                     \
        for (int p = 0; p < 4; ++p) {                                         \
            const int cid = tid + (p << 8);                                   \
            const int row = cid >> 3, c4 = cid & 7;                           \
            const uint32_t sw = row * 128 + ((c4 ^ (row & 7)) << 4);          \
            cpasync16(sA_ + sw, Ab + (size_t)row * K + kof_ + c4 * 8);        \
        }                                                                     \
        _Pragma("unroll")                                                     \
        for (int p = 0; p < 8; ++p) {                                         \
            const int cid = tid + (p << 8);                                   \
            const int row = cid >> 3, c4 = cid & 7;                           \
            const uint32_t sw = row * 128 + ((c4 ^ (row & 7)) << 4);          \
            cpasync16(sB_ + sw, Bb + (size_t)row * K + kof_ + c4 * 8);        \
        }                                                                     \
    }

    G_LOAD(0); CP_COMMIT();
    G_LOAD(1); CP_COMMIT();
    G_LOAD(2); CP_COMMIT();

    float acc[4][8][4];
#pragma unroll
    for (int i = 0; i < 4; i++)
#pragma unroll
        for (int j = 0; j < 8; j++)
#pragma unroll
            for (int r = 0; r < 4; r++) acc[i][j][r] = 0.f;

    for (int kt = 0; kt < nk; ++kt) {
        CP_WAIT2();
        __syncthreads();
        if (kt + 3 < nk) G_LOAD(kt + 3);
        CP_COMMIT();

        const uint32_t sA = s0 + (kt & 3) * GSTAGE, sB = sA + 16384;
#pragma unroll
        for (int kk = 0; kk < 4; ++kk) {
            uint32_t af[4][4], bf[4][4];
            const int ch = (kk << 1) + lh;
#pragma unroll
            for (int i = 0; i < 4; ++i) {
                const int row = wm + i * 16 + l15;
                LDSM4(af[i], sA + row * 128 + ((ch ^ (row & 7)) << 4));
            }
#pragma unroll
            for (int jp = 0; jp < 4; ++jp) {
                const int row = wn + jp * 16 + l15;
                LDSM4(bf[jp], sB + row * 128 + ((ch ^ (row & 7)) << 4));
            }
#pragma unroll
            for (int i = 0; i < 4; ++i)
#pragma unroll
                for (int jp = 0; jp < 4; ++jp) {
                    mma_h(acc[i][2*jp],   af[i], bf[jp][0], bf[jp][2]);
                    mma_h(acc[i][2*jp+1], af[i], bf[jp][1], bf[jp][3]);
                }
        }
    }
#undef G_LOAD

    const int g = lane >> 2, tg = lane & 3;
    const int rowbase = blockIdx.y * 128 + wm;
    const int colbase = blockIdx.x * 256 + wn;
#pragma unroll
    for (int i = 0; i < 4; ++i) {
#pragma unroll
        for (int j = 0; j < 8; ++j) {
            const int r0 = rowbase + i * 16 + g;
            const int c0 = colbase + j * 8 + tg * 2;
            const float bia0 = bias[c0], bia1 = bias[c0 + 1];
#pragma unroll
            for (int hr = 0; hr < 2; ++hr) {
                const int row = r0 + hr * 8;
                float v0 = acc[i][j][hr * 2 + 0] + bia0;
                float v1 = acc[i][j][hr * 2 + 1] + bia1;
                if (RES) {
                    v0 += Resid[(size_t)row * N + c0];
                    v1 += Resid[(size_t)row * N + c0 + 1];
                }
                if (ACT == ACT_GELU) {
                    v0 = 0.5f * v0 * (1.f + erff(v0 * 0.7071067811865475f));
                    v1 = 0.5f * v1 * (1.f + erff(v1 * 0.7071067811865475f));
                }
                if (OUTH) {
                    __half* Cb = (__half*)Cv + (size_t)z * cZ;
                    *(uint32_t*)&Cb[(size_t)row * ldC + c_off + c0] = packh2(v0, v1);
                } else {
                    float* Cb = (float*)Cv + (size_t)z * cZ;
                    *(float2*)&Cb[(size_t)row * ldC + c_off + c0] = make_float2(v0, v1);
                }
            }
        }
    }
}

// ---------------- per-head rmsnorm + rope (fp16 in-place, single tensor) ----
__global__ __launch_bounds__(256) void qknorm_rope_kernel(
    __half* __restrict__ x, const float* __restrict__ w,
    const float* __restrict__ freqs)
{
    const int token = blockIdx.x;
    const int pos = token & (SEQ - 1);
    const int warp = threadIdx.x >> 5, lane = threadIdx.x & 31;
    __shared__ float rb[8][32];
    const float4 wv = ((const float4*)w)[lane];
#pragma unroll
    for (int hh = 0; hh < 2; hh++) {
        const int h = warp + hh * 8;
        __half* p = x + (size_t)token * DMODEL + h * HDIM;
        uint2 raw = ((uint2*)p)[lane];
        const __half2 h0 = *(__half2*)&raw.x, h1 = *(__half2*)&raw.y;
        float v0 = __low2float(h0), v1 = __high2float(h0);
        float v2 = __low2float(h1), v3 = __high2float(h1);
        float ssq = v0*v0 + v1*v1 + v2*v2 + v3*v3;
#pragma unroll
        for (int o = 16; o; o >>= 1) ssq += __shfl_xor_sync(0xffffffffu, ssq, o);
        const float inv = rsqrtf(ssq * (1.f / HDIM) + EPSV);
        float o0 = v0 * inv * wv.x, o1 = v1 * inv * wv.y;
        float o2 = v2 * inv * wv.z, o3 = v3 * inv * wv.w;
        const int d0 = lane * 4;
        if (d0 < 32) {
            rb[warp][d0] = o0; rb[warp][d0 + 1] = o1;
            rb[warp][d0 + 2] = o2; rb[warp][d0 + 3] = o3;
        }
        __syncwarp();
        if (d0 < 32) {
            float r[4];
#pragma unroll
            for (int i = 0; i < 4; i++) {
                const int d = d0 + i, ii = d >> 1;
                const float x1 = rb[warp][ii], x2 = rb[warp][ii + 16];
                const float c  = freqs[pos * 32 + ii * 2];
                const float sn = freqs[pos * 32 + ii * 2 + 1];
                r[i] = (d & 1) ? (x2 * c + x1 * sn) : (x1 * c - x2 * sn);
            }
            o0 = r[0]; o1 = r[1]; o2 = r[2]; o3 = r[3];
        }
        __syncwarp();
        raw.x = packh2(o0, o1);
        raw.y = packh2(o2, o3);
        ((uint2*)p)[lane] = raw;
    }
}

// ---------------- causal flash attention (fp16 mma), per-batch --------------
#define ASTAGE 16384
#define ASMEM  (4 * ASTAGE)

__global__ __launch_bounds__(128, 3) void attn_h_kernel(
    const __half* __restrict__ Q, const __half* __restrict__ Kx,
    const __half* __restrict__ Vx, __half* __restrict__ O, int b)
{
    extern __shared__ char smem[];
    const uint32_t s0 = smem_u32(smem);
    const int tid = threadIdx.x;
    const int warp = tid >> 5, lane = tid & 31;
    const int g = lane >> 2, tg = lane & 3;
    const int l15 = lane & 15, lh = lane >> 4;
    const int qb = gridDim.x - 1 - blockIdx.x;
    const int h = blockIdx.y;
    const size_t base = ((size_t)b * SEQ) * DMODEL + h * HDIM;
    const size_t obase = ((size_t)b * SEQ) * KC2 + h * HDIM;
    const int q0 = qb * 64;
    const int wq = warp * 16;
    const int nkt = (q0 >> 5) + 2;
    const int r0 = q0 + wq + g, r1 = r0 + 8;

    uint32_t aq[8][4];
    {
        const __half* q_r0 = Q + base + (size_t)r0 * DMODEL;
        const __half* q_r1 = q_r0 + (size_t)8 * DMODEL;
#pragma unroll
        for (int kk = 0; kk < 8; ++kk) {
            aq[kk][0] = *(const uint32_t*)(q_r0 + kk * 16 + tg * 2);
            aq[kk][1] = *(const uint32_t*)(q_r1 + kk * 16 + tg * 2);
            aq[kk][2] = *(const uint32_t*)(q_r0 + kk * 16 + 8 + tg * 2);
            aq[kk][3] = *(const uint32_t*)(q_r1 + kk * 16 + 8 + tg * 2);
        }
    }

#define A_LOAD(kt)                                                            \
    {                                                                         \
        const int st_ = (kt) & 3;                                             \
        const uint32_t Kst_ = s0 + st_ * ASTAGE;                              \
        const uint32_t Vst_ = Kst_ + 8192;                                    \
        const int kv0_ = (kt) << 5;                                           \
        _Pragma("unroll")                                                     \
        for (int p = 0; p < 4; ++p) {                                         \
            const int cid = tid + (p << 7);                                   \
            const int row = cid >> 4, c = cid & 15;                           \
            const uint32_t sw = row * 256 + ((c ^ (row & 7)) << 4);           \
            const size_t go = base + (size_t)(kv0_ + row) * DMODEL + c * 8;   \
            cpasync16(Kst_ + sw, Kx + go);                                    \
            cpasync16(Vst_ + sw, Vx + go);                                    \
        }                                                                     \
    }

    A_LOAD(0); CP_COMMIT();
    A_LOAD(1); CP_COMMIT();
    A_LOAD(2); CP_COMMIT();

    float m0 = -1e30f, m1 = -1e30f, l0 = 0.f, l1 = 0.f;
    float o[16][4];
#pragma unroll
    for (int nb = 0; nb < 16; ++nb)
#pragma unroll
        for (int r = 0; r < 4; ++r) o[nb][r] = 0.f;

    for (int kt = 0; kt < nkt; ++kt) {
        CP_WAIT2();
        __syncthreads();
        if (kt + 3 < nkt) A_LOAD(kt + 3);
        CP_COMMIT();

        const int kv0 = kt << 5;
        if (kv0 <= q0 + wq + 15) {
            const uint32_t Kst = s0 + (kt & 3) * ASTAGE;
            const uint32_t Vst = Kst + 8192;

            float sc[4][4];
#pragma unroll
            for (int jb = 0; jb < 4; ++jb)
#pragma unroll
                for (int r = 0; r < 4; ++r) sc[jb][r] = 0.f;
#pragma unroll
            for (int kk = 0; kk < 8; ++kk) {
                const int ch = (kk << 1) + lh;
#pragma unroll
                for (int jp = 0; jp < 2; ++jp) {
                    uint32_t bf[4];
                    const int row = jp * 16 + l15;
                    LDSM4(bf, Kst + row * 256 + ((ch ^ (row & 7)) << 4));
                    mma_h(sc[2*jp],   aq[kk], bf[0], bf[2]);
                    mma_h(sc[2*jp+1], aq[kk], bf[1], bf[3]);
                }
            }

            const bool diag = (kv0 + 31 > r0) || (kv0 + 31 > r1);
#pragma unroll
            for (int jb = 0; jb < 4; ++jb) {
                const int c0 = kv0 + jb * 8 + tg * 2;
                sc[jb][0] *= SCALE_ATT; sc[jb][1] *= SCALE_ATT;
                sc[jb][2] *= SCALE_ATT; sc[jb][3] *= SCALE_ATT;
                if (diag) {
                    if (c0     > r0) sc[jb][0] = -1e30f;
                    if (c0 + 1 > r0) sc[jb][1] = -1e30f;
                    if (c0     > r1) sc[jb][2] = -1e30f;
                    if (c0 + 1 > r1) sc[jb][3] = -1e30f;
                }
            }

            float rm0 = sc[0][0], rm1 = sc[0][2];
#pragma unroll
            for (int jb = 0; jb < 4; ++jb) {
                rm0 = fmaxf(rm0, fmaxf(sc[jb][0], sc[jb][1]));
                rm1 = fmaxf(rm1, fmaxf(sc[jb][2], sc[jb][3]));
            }
            rm0 = fmaxf(rm0, __shfl_xor_sync(0xffffffffu, rm0, 1));
            rm0 = fmaxf(rm0, __shfl_xor_sync(0xffffffffu, rm0, 2));
            rm1 = fmaxf(rm1, __shfl_xor_sync(0xffffffffu, rm1, 1));
            rm1 = fmaxf(rm1, __shfl_xor_sync(0xffffffffu, rm1, 2));
            const float mx0 = fmaxf(m0, rm0), mx1 = fmaxf(m1, rm1);
            const float corr0 = __expf(m0 - mx0), corr1 = __expf(m1 - mx1);
            float rs0 = 0.f, rs1 = 0.f;
#pragma unroll
            for (int jb = 0; jb < 4; ++jb) {
                sc[jb][0] = __expf(sc[jb][0] - mx0);
                sc[jb][1] = __expf(sc[jb][1] - mx0);
                sc[jb][2] = __expf(sc[jb][2] - mx1);
                sc[jb][3] = __expf(sc[jb][3] - mx1);
                rs0 += sc[jb][0] + sc[jb][1];
                rs1 += sc[jb][2] + sc[jb][3];
            }
            rs0 += __shfl_xor_sync(0xffffffffu, rs0, 1);
            rs0 += __shfl_xor_sync(0xffffffffu, rs0, 2);
            rs1 += __shfl_xor_sync(0xffffffffu, rs1, 1);
            rs1 += __shfl_xor_sync(0xffffffffu, rs1, 2);
            l0 = l0 * corr0 + rs0;  m0 = mx0;
            l1 = l1 * corr1 + rs1;  m1 = mx1;
#pragma unroll
            for (int nb = 0; nb < 16; ++nb) {
                o[nb][0] *= corr0; o[nb][1] *= corr0;
                o[nb][2] *= corr1; o[nb][3] *= corr1;
            }

#pragma unroll
            for (int kc = 0; kc < 2; ++kc) {
                uint32_t pa[4];
                pa[0] = packh2(sc[2*kc][0],   sc[2*kc][1]);
                pa[1] = packh2(sc[2*kc][2],   sc[2*kc][3]);
                pa[2] = packh2(sc[2*kc+1][0], sc[2*kc+1][1]);
                pa[3] = packh2(sc[2*kc+1][2], sc[2*kc+1][3]);
#pragma unroll
                for (int cp = 0; cp < 8; ++cp) {
                    uint32_t vf[4];
                    const int row = kc * 16 + l15;
                    const int ch = (cp << 1) + lh;
                    LDSM4T(vf, Vst + row * 256 + ((ch ^ (row & 7)) << 4));
                    mma_h(o[2*cp],   pa, vf[0], vf[1]);
                    mma_h(o[2*cp+1], pa, vf[2], vf[3]);
                }
            }
        }
    }
#undef A_LOAD

    const float inv0 = 1.f / l0, inv1 = 1.f / l1;
    __half* o_r0 = O + obase + (size_t)r0 * KC2;
    __half* o_r1 = O + obase + (size_t)r1 * KC2;
#pragma unroll
    for (int nb = 0; nb < 16; ++nb) {
        const int c = nb * 8 + tg * 2;
        *(uint32_t*)&o_r0[c] = packh2(o[nb][0] * inv0, o[nb][1] * inv0);
        *(uint32_t*)&o_r1[c] = packh2(o[nb][2] * inv1, o[nb][3] * inv1);
    }
}

// ---------------- launcher --------------------------------------------------
static cudaStream_t g_side = nullptr, g_side2 = nullptr;
static cudaEvent_t g_ev0 = nullptr, g_evck = nullptr, g_evcqv = nullptr,
                   g_evlnr = nullptr, g_evj0 = nullptr, g_evj1 = nullptr,
                   g_evk = nullptr, g_evrk = nullptr, g_evrq = nullptr,
                   g_evF1 = nullptr;

extern "C" void kernel_launch(void* const* d_in, const int* in_sizes, int n_in,
                              void* d_out, int out_size)
{
    const float* x0      = (const float*)d_in[0];
    const float* x1      = (const float*)d_in[1];
    const float* x2      = (const float*)d_in[2];
    const float* x3      = (const float*)d_in[3];
    const float* freqs   = (const float*)d_in[5];
    const float* wq_w    = (const float*)d_in[7];
    const float* wq_b    = (const float*)d_in[8];
    const float* wk_w    = (const float*)d_in[9];
    const float* wk_b    = (const float*)d_in[10];
    const float* wv_w    = (const float*)d_in[11];
    const float* wv_b    = (const float*)d_in[12];
    const float* wo_w    = (const float*)d_in[13];
    const float* wo_b    = (const float*)d_in[14];
    const float* qn_w    = (const float*)d_in[15];
    const float* kn_w    = (const float*)d_in[16];
    const float* ln0_w   = (const float*)d_in[17];
    const float* ln0_b   = (const float*)d_in[18];
    const float* ln1_w   = (const float*)d_in[19];
    const float* ln1_b   = (const float*)d_in[20];
    const float* ln2_w   = (const float*)d_in[21];
    const float* ln2_b   = (const float*)d_in[22];
    const float* ffn_w   = (const float*)d_in[23];
    const float* ffn_b   = (const float*)d_in[24];
    const float* w1_w    = (const float*)d_in[25];
    const float* w1_b    = (const float*)d_in[26];
    const float* w2_w    = (const float*)d_in[27];
    const float* w2_b    = (const float*)d_in[28];
    float* out = (float*)d_out;

    __half* hs = nullptr;
    float* biasOW = nullptr;
    cudaGetSymbolAddress((void**)&hs, g_h);
    cudaGetSymbolAddress((void**)&biasOW, g_bias);
    __half* nq   = hs;                       // 3*CH (nq,nk,nv)
    __half* nk   = hs + CH;
    __half* nv   = hs + 2 * CH;
    __half* fx   = hs + 3 * CH;
    __half* q    = hs + 4 * CH;
    __half* k    = hs + 5 * CH;
    __half* v    = hs + 6 * CH;
    __half* yc   = hs + 7 * CH;              // [TOK, KC2]
    __half* wq_r = yc + (size_t)TOK * KC2;
    __half* wk_r = wq_r + WQKVO_SZ;
    __half* wv_r = wk_r + WQKVO_SZ;
    __half* w1_r = wv_r + WQKVO_SZ;
    __half* wow2 = w1_r + W12_SZ;            // [DMODEL, KC2]

    if (!g_side) {
        int lo = 0, hi = 0;
        cudaDeviceGetStreamPriorityRange(&lo, &hi);
        cudaStreamCreateWithPriority(&g_side, cudaStreamNonBlocking, lo);
        cudaStreamCreateWithFlags(&g_side2, cudaStreamNonBlocking);
        cudaEventCreateWithFlags(&g_ev0,   cudaEventDisableTiming);
        cudaEventCreateWithFlags(&g_evck,  cudaEventDisableTiming);
        cudaEventCreateWithFlags(&g_evcqv, cudaEventDisableTiming);
        cudaEventCreateWithFlags(&g_evlnr, cudaEventDisableTiming);
        cudaEventCreateWithFlags(&g_evj0,  cudaEventDisableTiming);
        cudaEventCreateWithFlags(&g_evj1,  cudaEventDisableTiming);
        cudaEventCreateWithFlags(&g_evk,   cudaEventDisableTiming);
        cudaEventCreateWithFlags(&g_evrk,  cudaEventDisableTiming);
        cudaEventCreateWithFlags(&g_evrq,  cudaEventDisableTiming);
        cudaEventCreateWithFlags(&g_evF1,  cudaEventDisableTiming);
    }

    cudaFuncSetAttribute(gemm_h_kernel<ACT_NONE, false, true>,
                         cudaFuncAttributeMaxDynamicSharedMemorySize, GSMEM);
    cudaFuncSetAttribute(gemm_h_kernel<ACT_NONE, true, false>,
                         cudaFuncAttributeMaxDynamicSharedMemorySize, GSMEM);
    cudaFuncSetAttribute(gemm_h_kernel<ACT_GELU, false, true>,
                         cudaFuncAttributeMaxDynamicSharedMemorySize, GSMEM);
    cudaFuncSetAttribute(attn_h_kernel,
                         cudaFuncAttributeMaxDynamicSharedMemorySize, ASMEM);

    const int nw4 = (int)(WQKVO_SZ / 4), nh4 = (int)(W12_SZ / 4);

    // fork both side streams
    cudaEventRecord(g_ev0, 0);
    cudaStreamWaitEvent(g_side, g_ev0, 0);
    cudaStreamWaitEvent(g_side2, g_ev0, 0);

    // side: wk first (gates K-proj), then wq/wv, then wo/w1/w2, bias
    round_one_kernel<<<(nw4 + 255) / 256, 256, 0, g_side>>>(
        (const float4*)wk_w, (uint2*)wk_r, nw4);
    cudaEventRecord(g_evck, g_side);
    round_qv_kernel<<<dim3((nw4 + 255) / 256, 2), 256, 0, g_side>>>(
        (const float4*)wq_w, (const float4*)wv_w,
        (uint2*)wq_r, (uint2*)wv_r, nw4);
    cudaEventRecord(g_evcqv, g_side);
    round_rest_kernel<<<dim3((nh4 + 255) / 256, 3), 256, 0, g_side>>>(
        (const float4*)wo_w, (const float4*)w1_w, (const float4*)w2_w,
        wow2, (uint2*)w1_r, nw4, nh4);
    bias_sum_kernel<<<(DMODEL + 255) / 256, 256, 0, g_side>>>(wo_b, w2_b, biasOW);

    // side2: LN for nq, nv, fx (independent of K path)
    layernorm3_kernel<<<dim3(TOK, 3), 256, 0, g_side2>>>(
        x0, x2, x3, ln0_w, ln2_w, ffn_w, ln0_b, ln2_b, ffn_b,
        nq, nv, fx);
    cudaEventRecord(g_evlnr, g_side2);

    // main: LN-k only (gates K-proj)
    layernorm1_kernel<<<TOK, 256>>>(x1, ln1_w, ln1_b, nk);

    // side: ffn1 in two halves (needs w1 conv in-order + fx from side2)
    cudaStreamWaitEvent(g_side, g_evlnr, 0);
    dim3 g1h(HID / 256, SEQ / 128, 1);
    gemm_h_kernel<ACT_GELU, false, true><<<g1h, 256, GSMEM, g_side>>>(
        fx, w1_r, w1_b, nullptr, nullptr, nullptr, yc,
        SEQ, HID, DMODEL, KC2, DMODEL, 0, 0, 0);
    cudaEventRecord(g_evj0, g_side);
    gemm_h_kernel<ACT_GELU, false, true><<<g1h, 256, GSMEM, g_side>>>(
        fx + (size_t)SEQ * DMODEL, w1_r, w1_b, nullptr, nullptr, nullptr,
        yc + (size_t)SEQ * KC2,
        SEQ, HID, DMODEL, KC2, DMODEL, 0, 0, 0);
    cudaEventRecord(g_evj1, g_side);

    // main: K projection (needs wk conv + LN-k)
    cudaStreamWaitEvent(0, g_evck, 0);
    dim3 gk(DMODEL / 256, TOK / 128, 1);
    gemm_h_kernel<ACT_NONE, false, true><<<gk, 256, GSMEM>>>(
        nk, wk_r, wk_b, nullptr, nullptr, nullptr, k,
        TOK, DMODEL, DMODEL, DMODEL, 0, 0, 0, 0);
    cudaEventRecord(g_evk, 0);

    // side2: rope-k concurrently with Q/V projection
    cudaStreamWaitEvent(g_side2, g_evk, 0);
    qknorm_rope_kernel<<<TOK, 256, 0, g_side2>>>(k, kn_w, freqs);
    cudaEventRecord(g_evrk, g_side2);

    // main: Q + V projection (needs wq/wv conv + nq/nv from side2)
    cudaStreamWaitEvent(0, g_evcqv, 0);
    cudaStreamWaitEvent(0, g_evlnr, 0);
    dim3 gqv(DMODEL / 256, TOK / 128, 2);
    gemm_h_kernel<ACT_NONE, false, true><<<gqv, 256, GSMEM>>>(
        nq, wq_r, wq_b, wv_b, nullptr, nullptr, q,
        TOK, DMODEL, DMODEL, DMODEL, 0, 2 * CH, 2 * WQKVO_SZ, 2 * CH);

    // main: rope-q
    qknorm_rope_kernel<<<TOK, 256>>>(q, qn_w, freqs);
    cudaEventRecord(g_evrq, 0);

    // main: attention batch 0 (needs rope-k from side2)
    cudaStreamWaitEvent(0, g_evrk, 0);
    attn_h_kernel<<<dim3(SEQ / 64, NHEAD), 128, ASMEM>>>(q, k, v, yc, 0);

    // side2: attention batch 1, concurrent with batch 0
    cudaStreamWaitEvent(g_side2, g_evrq, 0);
    attn_h_kernel<<<dim3(SEQ / 64, NHEAD), 128, ASMEM, g_side2>>>(q, k, v, yc, 1);

    // main: fused O+FFN2 half 0 (rows 0..2047) after attn b0 + ffn1 half 0
    cudaStreamWaitEvent(0, g_evj0, 0);
    dim3 gf(DMODEL / 256, SEQ / 128, 1);
    gemm_h_kernel<ACT_NONE, true, false><<<gf, 256, GSMEM>>>(
        yc, wow2, biasOW, nullptr, nullptr, x3, out,
        SEQ, DMODEL, KC2, DMODEL, 0, 0, 0, 0);

    // side2: fused O+FFN2 half 1 after attn b1 + ffn1 half 1
    cudaStreamWaitEvent(g_side2, g_evj1, 0);
    gemm_h_kernel<ACT_NONE, true, false><<<gf, 256, GSMEM, g_side2>>>(
        yc + (size_t)SEQ * KC2, wow2, biasOW, nullptr, nullptr,
        x3 + (size_t)SEQ * DMODEL, out + (size_t)SEQ * DMODEL,
        SEQ, DMODEL, KC2, DMODEL, 0, 0, 0, 0);
    cudaEventRecord(g_evF1, g_side2);

    // join side2 into main so the captured graph covers fused half 1
    cudaStreamWaitEvent(0, g_evF1, 0);
}